// round 13
// baseline (speedup 1.0000x reference)
#include <cuda_runtime.h>
#include <cuda_bf16.h>
#include <math.h>
#include <stdint.h>

#define NBg  64
#define NPGC 20
#define HD   512
#define TDC  256
#define NFC  128
#define NLC  6
#define AC   100
#define NN   1280
#define EE   24320
#define KP2  832       /* 3 + 768 padded to 26*32 */
#define TWO_PI_F 6.283185307179586f

// ---------------- scratch ----------------
__device__ __nv_bfloat16 g_Ahi[(size_t)EE * KP2];
__device__ __nv_bfloat16 g_Alo[(size_t)EE * KP2];
__device__ __nv_bfloat16 g_e1hi[(size_t)EE * HD];
__device__ __nv_bfloat16 g_e1lo[(size_t)EE * HD];
__device__ __nv_bfloat16 g_Wt1hi[(size_t)NLC * HD * KP2];
__device__ __nv_bfloat16 g_Wt1lo[(size_t)NLC * HD * KP2];
__device__ __nv_bfloat16 g_Wt2hi[(size_t)NLC * HD * HD];
__device__ __nv_bfloat16 g_Wt2lo[(size_t)NLC * HD * HD];
__device__ __nv_bfloat16 g_Wsdhi[(size_t)NLC * 1024 * HD];   // [src(512) ; dst(512)] rows
__device__ __nv_bfloat16 g_Wsdlo[(size_t)NLC * 1024 * HD];
__device__ __nv_bfloat16 g_Wn1thi[(size_t)NLC * HD * 2 * HD];
__device__ __nv_bfloat16 g_Wn1tlo[(size_t)NLC * HD * 2 * HD];
__device__ __nv_bfloat16 g_Wn2thi[(size_t)NLC * HD * HD];
__device__ __nv_bfloat16 g_Wn2tlo[(size_t)NLC * HD * HD];
__device__ __nv_bfloat16 g_hnhi[NN * HD];
__device__ __nv_bfloat16 g_hnlo[NN * HD];
__device__ __nv_bfloat16 g_ncathi[NN * 2 * HD];
__device__ __nv_bfloat16 g_ncatlo[NN * 2 * HD];
__device__ __nv_bfloat16 g_t1hi[NN * HD];
__device__ __nv_bfloat16 g_t1lo[NN * HD];
__device__ float g_h[NN * HD];
__device__ float g_hn[NN * HD];
__device__ float g_nps[NN * HD];
__device__ float g_npd[NN * HD];
__device__ float g_agg[NN * HD];
__device__ float g_gp[(size_t)NLC * NBg * HD];
__device__ float g_ltl[NBg * 9];
__device__ float g_counts[NN];
__device__ float g_sum[NBg * HD];
__device__ float g_nodeproj[AC * HD];
__device__ float g_sj[HD];

__device__ __forceinline__ float siluf(float x){ return x / (1.f + expf(-x)); }

#define MMA16816(c, a, b0_, b1_) \
    asm volatile("mma.sync.aligned.m16n8k16.row.col.f32.bf16.bf16.f32 " \
        "{%0,%1,%2,%3}, {%4,%5,%6,%7}, {%8,%9}, {%0,%1,%2,%3};" \
        : "+f"((c)[0]), "+f"((c)[1]), "+f"((c)[2]), "+f"((c)[3]) \
        : "r"((a)[0]), "r"((a)[1]), "r"((a)[2]), "r"((a)[3]), "r"(b0_), "r"(b1_))

// ---------------- small kernels ----------------
__global__ void k_zero(float* p, int n){
  for (int i = blockIdx.x*blockDim.x + threadIdx.x; i < n; i += gridDim.x*blockDim.x) p[i] = 0.f;
}

__global__ void k_graphprep(const float* __restrict__ lp){
  int g = blockIdx.x*blockDim.x + threadIdx.x;
  if (g >= NBg) return;
  const float LM0=1.575442910194397f, LM1=1.7017393112182617f, LM2=1.9781638383865356f;
  const float LS0=0.24437622725963593f, LS1=0.26526379585266113f, LS2=0.3535512685775757f;
  float l0 = expf(lp[g*6+0]*LS0+LM0);
  float l1 = expf(lp[g*6+1]*LS1+LM1);
  float l2 = expf(lp[g*6+2]*LS2+LM2);
  float ang[3];
  #pragma unroll
  for (int i=0;i<3;i++){
    float x = lp[g*6+3+i];
    float sg = 1.f/(1.f+expf(-x));
    ang[i] = (59.9f + 60.2f*sg) * 0.017453292519943295f;
  }
  float c0=cosf(ang[0]), c1=cosf(ang[1]), c2=cosf(ang[2]);
  float s0=sinf(ang[0]), s1=sinf(ang[1]);
  float val = (c0*c1 - c2)/(s0*s1);
  val = fminf(1.f, fmaxf(-1.f, val));
  float gs = acosf(val);
  float L[3][3];
  L[0][0]=l0*s1;            L[0][1]=0.f;             L[0][2]=l0*c1;
  L[1][0]=-l1*s0*cosf(gs);  L[1][1]=l1*s0*sinf(gs);  L[1][2]=l1*c0;
  L[2][0]=0.f;              L[2][1]=0.f;             L[2][2]=l2;
  #pragma unroll
  for (int i=0;i<3;i++)
    #pragma unroll
    for (int k=0;k<3;k++)
      g_ltl[g*9+i*3+k] = L[i][0]*L[k][0] + L[i][1]*L[k][1] + L[i][2]*L[k][2];
}

__global__ void k_sj(const float* __restrict__ Wt, const float* __restrict__ Wlat){
  int j = blockIdx.x*64 + threadIdx.x;
  float acc = 0.f;
  for (int k=0;k<TDC;k++) acc += Wt[k]*Wlat[(size_t)(512+k)*HD + j];
  g_sj[j] = acc;
}

__global__ void k_nodeproj(const float* __restrict__ Wn, const float* __restrict__ Wlat){
  int a = blockIdx.x, j = threadIdx.x;
  float acc = 0.f;
  for (int k=0;k<HD;k++) acc += Wn[a*HD+k]*Wlat[(size_t)k*HD + j];
  g_nodeproj[a*HD+j] = acc;
}

__global__ void k_hinit(const int* __restrict__ at, const int* __restrict__ n2g,
                        const float* __restrict__ t){
  int n = blockIdx.x, j = threadIdx.x;
  int a = at[n]-1; if (a < 0) a = 0;
  g_h[n*HD+j] = g_nodeproj[a*HD+j] + t[n2g[n]] * g_sj[j];
}

__device__ __forceinline__ void split_store(__nv_bfloat16* hi, __nv_bfloat16* lo, size_t idx, float v){
  __nv_bfloat16 h = __float2bfloat16(v);
  hi[idx] = h;
  lo[idx] = __float2bfloat16(v - __bfloat162float(h));
}

__global__ void k_edgeprep(const float* __restrict__ fc, const int* __restrict__ srcI,
                           const int* __restrict__ dstI, const int* __restrict__ e2gI){
  int e = blockIdx.x; int tid = threadIdx.x;  // 128 threads
  int s = srcI[e], d = dstI[e], g = e2gI[e];
  float fd[3];
  #pragma unroll
  for (int i=0;i<3;i++){
    float z = TWO_PI_F * (fc[d*3+i] - fc[s*3+i]);
    fd[i] = atan2f(sinf(z), cosf(z)) / TWO_PI_F;
  }
  size_t rb = (size_t)e*KP2;
  if (tid == 0){
    float dots[3]; float nrm = 0.f;
    #pragma unroll
    for (int i=0;i<3;i++){
      float acc = 0.f;
      #pragma unroll
      for (int j=0;j<3;j++) acc += g_ltl[g*9+i*3+j]*fd[j];
      dots[i] = acc; nrm += acc*acc;
    }
    nrm = sqrtf(nrm) + 1e-12f;
    #pragma unroll
    for (int i=0;i<3;i++) split_store(g_Ahi, g_Alo, rb+i, dots[i]/nrm);
    atomicAdd(&g_counts[s], 1.f);
  }
  if (tid >= 64 && tid < 64 + (KP2 - 771)){
    int c = 771 + tid - 64;
    g_Ahi[rb+c] = __float2bfloat16(0.f);
    g_Alo[rb+c] = __float2bfloat16(0.f);
  }
  for (int idx = tid; idx < 3*NFC; idx += blockDim.x){
    int i = idx >> 7, k = idx & 127;
    float arg = TWO_PI_F * (float)k * fd[i];
    float sv, cv; sincosf(arg, &sv, &cv);
    split_store(g_Ahi, g_Alo, rb + 3 + idx, sv);
    split_store(g_Ahi, g_Alo, rb + 3 + 384 + idx, cv);
  }
}

// ---- weight transposes/splits (N-major bf16 hi/lo), once per launch ----
__global__ void k_wt1(const float* __restrict__ We1){
  int b = blockIdx.x;                // NLC*HD blocks
  int l = b >> 9, n = b & 511;
  const float* W = We1 + (size_t)l*2313*HD;
  size_t ob = (size_t)b*KP2;
  for (int k = threadIdx.x; k < KP2; k += 256){
    float v = 0.f;
    if (k < 3) v = W[(size_t)k*HD + n];
    else if (k < 771) v = W[(size_t)(k+1030)*HD + n];
    split_store(g_Wt1hi, g_Wt1lo, ob + k, v);
  }
}
__global__ void k_wt2(const float* __restrict__ We2){
  int b = blockIdx.x;
  int l = b >> 9, n = b & 511;
  const float* W = We2 + (size_t)l*HD*HD;
  size_t ob = (size_t)b*HD;
  for (int k = threadIdx.x; k < HD; k += 256)
    split_store(g_Wt2hi, g_Wt2lo, ob + k, W[(size_t)k*HD + n]);
}
// We1 src/dst blocks combined: rows 0..511 = src (We1 rows 3..514), 512..1023 = dst (515..1026)
__global__ void k_wsd(const float* __restrict__ We1){
  int b = blockIdx.x;                // NLC*1024 blocks
  int l = b >> 10, n = b & 1023;
  const float* W = We1 + (size_t)l*2313*HD;
  int srow = (n < 512) ? (3 + n) : (515 + (n - 512));
  int ncol = (n < 512) ? n : (n - 512);
  (void)ncol;
  size_t ob = (size_t)b*HD;
  int wcol = (n < 512) ? n : (n - 512);
  for (int k = threadIdx.x; k < HD; k += 256)
    split_store(g_Wsdhi, g_Wsdlo, ob + k, W[(size_t)(srow - n + n)*0 + (size_t)((n < 512) ? (3+k) : (515+k))*HD + wcol]);
}

__global__ void k_wn1t(const float* __restrict__ Wn1){
  int b = blockIdx.x;                // NLC*HD blocks
  int l = b >> 9, n = b & 511;
  const float* W = Wn1 + (size_t)l*1024*HD;
  size_t ob = (size_t)b*1024;
  for (int k = threadIdx.x; k < 1024; k += 256)
    split_store(g_Wn1thi, g_Wn1tlo, ob + k, W[(size_t)k*HD + n]);
}
__global__ void k_wn2t(const float* __restrict__ Wn2){
  int b = blockIdx.x;
  int l = b >> 9, n = b & 511;
  const float* W = Wn2 + (size_t)l*HD*HD;
  size_t ob = (size_t)b*HD;
  for (int k = threadIdx.x; k < HD; k += 256)
    split_store(g_Wn2thi, g_Wn2tlo, ob + k, W[(size_t)k*HD + n]);
}

// LN -> fp32 y + bf16 hi/lo split
__global__ void k_ln(const float* __restrict__ x, float* __restrict__ y,
                     __nv_bfloat16* __restrict__ yhi, __nv_bfloat16* __restrict__ ylo,
                     const float* __restrict__ gamma, const float* __restrict__ beta){
  int n = blockIdx.x, t = threadIdx.x;  // 256
  float v0 = x[n*HD+t], v1 = x[n*HD+t+256];
  __shared__ float s1[256], s2[256];
  s1[t] = v0+v1; s2[t] = v0*v0 + v1*v1;
  __syncthreads();
  for (int o=128;o>0;o>>=1){
    if (t<o){ s1[t]+=s1[t+o]; s2[t]+=s2[t+o]; }
    __syncthreads();
  }
  float mu = s1[0] * (1.f/512.f);
  float var = s2[0] * (1.f/512.f) - mu*mu;
  float rs = rsqrtf(var + 1e-5f);
  float o0 = (v0-mu)*rs*gamma[t]     + beta[t];
  float o1 = (v1-mu)*rs*gamma[t+256] + beta[t+256];
  y[n*HD+t]     = o0;
  y[n*HD+t+256] = o1;
  split_store(yhi, ylo, (size_t)n*HD+t,     o0);
  split_store(yhi, ylo, (size_t)n*HD+t+256, o1);
}

// all-layer gp precompute: grid (NBg, NLC)
__global__ void k_gp_all(const float* __restrict__ lp, const int* __restrict__ na,
                         const float* __restrict__ We1, const float* __restrict__ Wna){
  int g = blockIdx.x, l = blockIdx.y, j = threadIdx.x;  // 512
  const float* We1l = We1 + (size_t)l*2313*HD;
  const float* Wnal = Wna + (size_t)l*AC*HD;
  float acc = 0.f;
  #pragma unroll
  for (int k=0;k<6;k++) acc += lp[g*6+k]*We1l[(size_t)(1027+k)*HD + j];
  int nr = na[g]-1; if (nr < 0) nr = 0;
  const float* wrow = Wnal + (size_t)nr*HD;
  for (int k=0;k<HD;k++) acc += wrow[k]*We1l[(size_t)(1801+k)*HD + j];
  g_gp[(size_t)l*NBg*HD + g*HD + j] = acc;
}

// ncat = [hn | agg/counts] as bf16 hi/lo
__global__ void k_ncat(){
  int n = blockIdx.x, j = threadIdx.x;  // 512
  float c = fmaxf(g_counts[n], 1.f);
  split_store(g_ncathi, g_ncatlo, (size_t)n*1024 + j,       g_hn[n*HD+j]);
  split_store(g_ncathi, g_ncatlo, (size_t)n*1024 + 512 + j, g_agg[n*HD+j] / c);
}

__global__ void k_pool(const int* __restrict__ n2g){
  int n = blockIdx.x, j = threadIdx.x;
  atomicAdd(&g_sum[n2g[n]*HD + j], g_hn[n*HD+j]);
}

__global__ void k_pos(const float* __restrict__ Wc, float* __restrict__ out){
  int n = blockIdx.x; int w = threadIdx.x >> 5; int lane = threadIdx.x & 31;
  float acc = 0.f;
  for (int j=lane;j<HD;j+=32) acc += g_hn[n*HD+j]*Wc[j*3+w];
  #pragma unroll
  for (int o=16;o;o>>=1) acc += __shfl_down_sync(0xffffffffu, acc, o);
  if (lane==0) out[n*3+w] = acc;
}

__global__ void k_cell(const int* __restrict__ na, const float* __restrict__ Wlo,
                       const float* __restrict__ blo, float* __restrict__ out){
  int g = blockIdx.x; int o = threadIdx.x >> 5; int lane = threadIdx.x & 31;
  if (o >= 6) return;
  float nav = (float)na[g];
  float acc = 0.f;
  for (int j=lane;j<HD;j+=32){
    float s = g_sum[g*HD+j];
    acc += s*(Wlo[j*6+o]/nav + Wlo[(size_t)(HD+j)*6+o]);
  }
  #pragma unroll
  for (int off=16;off;off>>=1) acc += __shfl_down_sync(0xffffffffu, acc, off);
  if (lane==0) out[NN*3 + g*6 + o] = acc + blo[o];
}

// ---------------- HMMA GEMM: block 128x128, k-step 32, bf16 3-term split ----
// Double-buffered dynamic smem; one __syncthreads per k-step.
// MODE 0: e1 = silu(acc + bias + nps[src]+npd[dst]+gp[e2g]) -> bf16 hi/lo (edge MLP-1)
// MODE 1: atomicAdd(agg[src], silu(acc + bias))                       (edge MLP-2)
// MODE 2: fp32 plain store; cols<512 -> fC, cols>=512 -> fC2          (nps+npd fused)
// MODE 3: silu(acc + bias) -> bf16 hi/lo                               (node t1)
// MODE 4: fC += silu(acc + bias) (fp32 residual)                       (node h)
#define SAS 40                    /* smem row stride in bf16 (32 + 8 pad) */
#define STG_ELEMS (128*SAS)       /* per array per stage */
#define STG_BYTES (4*STG_ELEMS*2) /* 4 arrays */
#define HMMA_SMEM (2*STG_BYTES)   /* 81920 B */
template<int MODE>
__global__ void __launch_bounds__(256,2)
hmma(const __nv_bfloat16* __restrict__ Ahi, const __nv_bfloat16* __restrict__ Alo,
     const __nv_bfloat16* __restrict__ Bhi, const __nv_bfloat16* __restrict__ Blo,
     int KT,
     const float* __restrict__ bias,
     const float* __restrict__ nps, const float* __restrict__ npd, const float* __restrict__ gp,
     const int* __restrict__ srcI, const int* __restrict__ dstI, const int* __restrict__ e2gI,
     __nv_bfloat16* __restrict__ outhi, __nv_bfloat16* __restrict__ outlo,
     float* __restrict__ fC, float* __restrict__ fC2)
{
  extern __shared__ __nv_bfloat16 dynsmem[];

  int tid = threadIdx.x, wid = tid >> 5, lane = tid & 31;
  int warp_m = wid & 3, warp_n = wid >> 2;     // 4 x 2 warp grid
  int rowBlock = blockIdx.y * 128;
  int colBlock = blockIdx.x * 128;

  float acc[2][8][4];
  #pragma unroll
  for (int i=0;i<2;i++)
    #pragma unroll
    for (int j=0;j<8;j++)
      #pragma unroll
      for (int q=0;q<4;q++) acc[i][j][q] = 0.f;

  // gmem load mapping: thread -> (row = tid>>1, 16-bf16 half = tid&1), 2 uint4 each
  int lrow = tid >> 1, lcol = (tid & 1) * 16;
  const __nv_bfloat16* gAh = Ahi + (size_t)(rowBlock + lrow)*KT + lcol;
  const __nv_bfloat16* gAl = Alo + (size_t)(rowBlock + lrow)*KT + lcol;
  const __nv_bfloat16* gBh = Bhi + (size_t)(colBlock + lrow)*KT + lcol;
  const __nv_bfloat16* gBl = Blo + (size_t)(colBlock + lrow)*KT + lcol;

  int frow = lane >> 2;          // 0..7
  int fk   = (lane & 3) * 2;     // 0,2,4,6

  const int nsteps = KT >> 5;
  int sidx = lrow*SAS + lcol;

  // preload stage 0
  {
    __nv_bfloat16* st = dynsmem;
    *(uint4*)&st[0*STG_ELEMS + sidx]     = *(const uint4*)(gAh);
    *(uint4*)&st[0*STG_ELEMS + sidx + 8] = *(const uint4*)(gAh + 8);
    *(uint4*)&st[1*STG_ELEMS + sidx]     = *(const uint4*)(gAl);
    *(uint4*)&st[1*STG_ELEMS + sidx + 8] = *(const uint4*)(gAl + 8);
    *(uint4*)&st[2*STG_ELEMS + sidx]     = *(const uint4*)(gBh);
    *(uint4*)&st[2*STG_ELEMS + sidx + 8] = *(const uint4*)(gBh + 8);
    *(uint4*)&st[3*STG_ELEMS + sidx]     = *(const uint4*)(gBl);
    *(uint4*)&st[3*STG_ELEMS + sidx + 8] = *(const uint4*)(gBl + 8);
  }
  __syncthreads();

  for (int s = 0; s < nsteps; s++){
    __nv_bfloat16* cur = dynsmem + (s & 1) * (4*STG_ELEMS);
    __nv_bfloat16* nxt = dynsmem + ((s & 1) ^ 1) * (4*STG_ELEMS);
    const __nv_bfloat16* sAh = cur + 0*STG_ELEMS;
    const __nv_bfloat16* sAl = cur + 1*STG_ELEMS;
    const __nv_bfloat16* sBh = cur + 2*STG_ELEMS;
    const __nv_bfloat16* sBl = cur + 3*STG_ELEMS;

    uint4 a0,a1,a2,a3,b0,b1,b2,b3;
    bool more = (s + 1 < nsteps);
    if (more){
      int o = (s+1)*32;
      a0 = *(const uint4*)(gAh + o);
      a1 = *(const uint4*)(gAh + o + 8);
      a2 = *(const uint4*)(gAl + o);
      a3 = *(const uint4*)(gAl + o + 8);
      b0 = *(const uint4*)(gBh + o);
      b1 = *(const uint4*)(gBh + o + 8);
      b2 = *(const uint4*)(gBl + o);
      b3 = *(const uint4*)(gBl + o + 8);
    }

    #pragma unroll
    for (int kk = 0; kk < 32; kk += 16){
      uint32_t ah[2][4], al[2][4];
      #pragma unroll
      for (int mt = 0; mt < 2; mt++){
        int abase = warp_m*32 + mt*16 + frow;
        #pragma unroll
        for (int j = 0; j < 4; j++){
          int row = abase + (j & 1)*8;
          int kc  = kk + fk + (j >> 1)*8;
          ah[mt][j] = *(const uint32_t*)&sAh[row*SAS + kc];
          al[mt][j] = *(const uint32_t*)&sAl[row*SAS + kc];
        }
      }
      #pragma unroll
      for (int nt = 0; nt < 8; nt++){
        int nrow = warp_n*64 + nt*8 + frow;
        uint32_t bh0 = *(const uint32_t*)&sBh[nrow*SAS + kk + fk];
        uint32_t bh1 = *(const uint32_t*)&sBh[nrow*SAS + kk + fk + 8];
        uint32_t bl0 = *(const uint32_t*)&sBl[nrow*SAS + kk + fk];
        uint32_t bl1 = *(const uint32_t*)&sBl[nrow*SAS + kk + fk + 8];
        #pragma unroll
        for (int mt = 0; mt < 2; mt++){
          MMA16816(acc[mt][nt], ah[mt], bh0, bh1);
          MMA16816(acc[mt][nt], ah[mt], bl0, bl1);
          MMA16816(acc[mt][nt], al[mt], bh0, bh1);
        }
      }
    }

    if (more){
      *(uint4*)&nxt[0*STG_ELEMS + sidx]     = a0;
      *(uint4*)&nxt[0*STG_ELEMS + sidx + 8] = a1;
      *(uint4*)&nxt[1*STG_ELEMS + sidx]     = a2;
      *(uint4*)&nxt[1*STG_ELEMS + sidx + 8] = a3;
      *(uint4*)&nxt[2*STG_ELEMS + sidx]     = b0;
      *(uint4*)&nxt[2*STG_ELEMS + sidx + 8] = b1;
      *(uint4*)&nxt[3*STG_ELEMS + sidx]     = b2;
      *(uint4*)&nxt[3*STG_ELEMS + sidx + 8] = b3;
    }
    __syncthreads();
  }

  // ---- epilogue ----
  int cbase = colBlock + warp_n*64 + (lane & 3)*2;
  float2 bvv[8];
  if (MODE != 2){
    #pragma unroll
    for (int nt = 0; nt < 8; nt++) bvv[nt] = *(const float2*)(bias + cbase + nt*8);
  }

  #pragma unroll
  for (int mt = 0; mt < 2; mt++){
    #pragma unroll
    for (int h = 0; h < 2; h++){
      int r = rowBlock + warp_m*32 + mt*16 + (lane >> 2) + h*8;
      if (MODE == 0){
        int s2 = srcI[r], d2 = dstI[r], g2 = e2gI[r];
        const float* np_s = nps + (size_t)s2*HD;
        const float* np_d = npd + (size_t)d2*HD;
        const float* gpp  = gp  + (size_t)g2*HD;
        __nv_bfloat16* oh = outhi + (size_t)r*HD;
        __nv_bfloat16* ol = outlo + (size_t)r*HD;
        #pragma unroll
        for (int nt = 0; nt < 8; nt++){
          int c = cbase + nt*8;
          float2 sv = *(const float2*)(np_s + c);
          float2 dv = *(const float2*)(np_d + c);
          float2 gv = *(const float2*)(gpp + c);
          float v0 = siluf(acc[mt][nt][h*2+0] + bvv[nt].x + sv.x + dv.x + gv.x);
          float v1 = siluf(acc[mt][nt][h*2+1] + bvv[nt].y + sv.y + dv.y + gv.y);
          __nv_bfloat16 h0 = __float2bfloat16(v0);
          __nv_bfloat16 h1 = __float2bfloat16(v1);
          __nv_bfloat162 hip; hip.x = h0; hip.y = h1;
          __nv_bfloat162 lop;
          lop.x = __float2bfloat16(v0 - __bfloat162float(h0));
          lop.y = __float2bfloat16(v1 - __bfloat162float(h1));
          *(__nv_bfloat162*)(oh + c) = hip;
          *(__nv_bfloat162*)(ol + c) = lop;
        }
      } else if (MODE == 1){
        int s2 = srcI[r];
        float* ao = fC + (size_t)s2*HD;
        #pragma unroll
        for (int nt = 0; nt < 8; nt++){
          int c = cbase + nt*8;
          atomicAdd(ao + c,     siluf(acc[mt][nt][h*2+0] + bvv[nt].x));
          atomicAdd(ao + c + 1, siluf(acc[mt][nt][h*2+1] + bvv[nt].y));
        }
      } else if (MODE == 2){
        // fused nps/npd: cols < 512 -> fC, >= 512 -> fC2
        float* fo = (cbase < 512) ? (fC + (size_t)r*HD) : (fC2 + (size_t)r*HD - 512);
        #pragma unroll
        for (int nt = 0; nt < 8; nt++){
          int c = cbase + nt*8;
          fo[c]     = acc[mt][nt][h*2+0];
          fo[c + 1] = acc[mt][nt][h*2+1];
        }
      } else if (MODE == 3){
        __nv_bfloat16* oh = outhi + (size_t)r*HD;
        __nv_bfloat16* ol = outlo + (size_t)r*HD;
        #pragma unroll
        for (int nt = 0; nt < 8; nt++){
          int c = cbase + nt*8;
          float v0 = siluf(acc[mt][nt][h*2+0] + bvv[nt].x);
          float v1 = siluf(acc[mt][nt][h*2+1] + bvv[nt].y);
          __nv_bfloat16 h0 = __float2bfloat16(v0);
          __nv_bfloat16 h1 = __float2bfloat16(v1);
          __nv_bfloat162 hip; hip.x = h0; hip.y = h1;
          __nv_bfloat162 lop;
          lop.x = __float2bfloat16(v0 - __bfloat162float(h0));
          lop.y = __float2bfloat16(v1 - __bfloat162float(h1));
          *(__nv_bfloat162*)(oh + c) = hip;
          *(__nv_bfloat162*)(ol + c) = lop;
        }
      } else {  // MODE 4
        float* fo = fC + (size_t)r*HD;
        #pragma unroll
        for (int nt = 0; nt < 8; nt++){
          int c = cbase + nt*8;
          fo[c]     += siluf(acc[mt][nt][h*2+0] + bvv[nt].x);
          fo[c + 1] += siluf(acc[mt][nt][h*2+1] + bvv[nt].y);
        }
      }
    }
  }
}

// ---------------- host ----------------
extern "C" void kernel_launch(void* const* d_in, const int* in_sizes, int n_in,
                              void* d_out, int out_size) {
  const float* t    = (const float*)d_in[0];
  const float* fc   = (const float*)d_in[1];
  const float* lp   = (const float*)d_in[2];
  const int*   at   = (const int*)d_in[3];
  const int*   na   = (const int*)d_in[4];
  const int*   n2g  = (const int*)d_in[5];
  const int*   eidx = (const int*)d_in[6];
  const int*   e2g  = (const int*)d_in[7];
  const float* W_node   = (const float*)d_in[8];
  const float* W_time   = (const float*)d_in[9];
  const float* W_latent = (const float*)d_in[10];
  const float* ln_g = (const float*)d_in[11];
  const float* ln_b = (const float*)d_in[12];
  const float* We1  = (const float*)d_in[13];
  const float* be1  = (const float*)d_in[14];
  const float* We2  = (const float*)d_in[15];
  const float* be2  = (const float*)d_in[16];
  const float* Wn1  = (const float*)d_in[17];
  const float* bn1  = (const float*)d_in[18];
  const float* Wn2  = (const float*)d_in[19];
  const float* bn2  = (const float*)d_in[20];
  const float* Wna  = (const float*)d_in[21];
  const float* fg   = (const float*)d_in[22];
  const float* fb   = (const float*)d_in[23];
  const float* Wc   = (const float*)d_in[24];
  const float* Wlo  = (const float*)d_in[25];
  const float* blo  = (const float*)d_in[26];
  const int* srcI = eidx;
  const int* dstI = eidx + EE;
  float* out = (float*)d_out;

  float *ph,*phn,*pnps,*pnpd,*pagg,*pgp,*pcounts,*psum;
  __nv_bfloat16 *pAhi,*pAlo,*pe1hi,*pe1lo,*pWt1hi,*pWt1lo,*pWt2hi,*pWt2lo;
  __nv_bfloat16 *pWsdhi,*pWsdlo,*pWn1thi,*pWn1tlo,*pWn2thi,*pWn2tlo;
  __nv_bfloat16 *phnhi,*phnlo,*pncathi,*pncatlo,*pt1hi,*pt1lo;
  cudaGetSymbolAddress((void**)&ph, g_h);
  cudaGetSymbolAddress((void**)&phn, g_hn);
  cudaGetSymbolAddress((void**)&pnps, g_nps);
  cudaGetSymbolAddress((void**)&pnpd, g_npd);
  cudaGetSymbolAddress((void**)&pagg, g_agg);
  cudaGetSymbolAddress((void**)&pgp, g_gp);
  cudaGetSymbolAddress((void**)&pcounts, g_counts);
  cudaGetSymbolAddress((void**)&psum, g_sum);
  cudaGetSymbolAddress((void**)&pAhi, g_Ahi);
  cudaGetSymbolAddress((void**)&pAlo, g_Alo);
  cudaGetSymbolAddress((void**)&pe1hi, g_e1hi);
  cudaGetSymbolAddress((void**)&pe1lo, g_e1lo);
  cudaGetSymbolAddress((void**)&pWt1hi, g_Wt1hi);
  cudaGetSymbolAddress((void**)&pWt1lo, g_Wt1lo);
  cudaGetSymbolAddress((void**)&pWt2hi, g_Wt2hi);
  cudaGetSymbolAddress((void**)&pWt2lo, g_Wt2lo);
  cudaGetSymbolAddress((void**)&pWsdhi, g_Wsdhi);
  cudaGetSymbolAddress((void**)&pWsdlo, g_Wsdlo);
  cudaGetSymbolAddress((void**)&pWn1thi, g_Wn1thi);
  cudaGetSymbolAddress((void**)&pWn1tlo, g_Wn1tlo);
  cudaGetSymbolAddress((void**)&pWn2thi, g_Wn2thi);
  cudaGetSymbolAddress((void**)&pWn2tlo, g_Wn2tlo);
  cudaGetSymbolAddress((void**)&phnhi, g_hnhi);
  cudaGetSymbolAddress((void**)&phnlo, g_hnlo);
  cudaGetSymbolAddress((void**)&pncathi, g_ncathi);
  cudaGetSymbolAddress((void**)&pncatlo, g_ncatlo);
  cudaGetSymbolAddress((void**)&pt1hi, g_t1hi);
  cudaGetSymbolAddress((void**)&pt1lo, g_t1lo);

  float* pnodeproj; cudaGetSymbolAddress((void**)&pnodeproj, g_nodeproj);

  static bool attr_done = false;
  if (!attr_done){
    cudaFuncSetAttribute(hmma<0>, cudaFuncAttributeMaxDynamicSharedMemorySize, HMMA_SMEM);
    cudaFuncSetAttribute(hmma<1>, cudaFuncAttributeMaxDynamicSharedMemorySize, HMMA_SMEM);
    cudaFuncSetAttribute(hmma<2>, cudaFuncAttributeMaxDynamicSharedMemorySize, HMMA_SMEM);
    cudaFuncSetAttribute(hmma<3>, cudaFuncAttributeMaxDynamicSharedMemorySize, HMMA_SMEM);
    cudaFuncSetAttribute(hmma<4>, cudaFuncAttributeMaxDynamicSharedMemorySize, HMMA_SMEM);
    attr_done = true;
  }

  dim3 blk(256);

  // -------- precompute --------
  k_graphprep<<<1, NBg>>>(lp);
  k_zero<<<8, 256>>>(pcounts, NN);
  k_edgeprep<<<EE, 128>>>(fc, srcI, dstI, e2g);
  k_wt1<<<NLC*HD, 256>>>(We1);
  k_wt2<<<NLC*HD, 256>>>(We2);
  k_wsd<<<NLC*1024, 256>>>(We1);
  k_wn1t<<<NLC*HD, 256>>>(Wn1);
  k_wn2t<<<NLC*HD, 256>>>(Wn2);
  k_gp_all<<<dim3(NBg, NLC), HD>>>(lp, na, We1, Wna);
  k_nodeproj<<<AC, HD>>>(W_node, W_latent);
  k_sj<<<8, 64>>>(W_time, W_latent);
  k_hinit<<<NN, HD>>>(at, n2g, t);

  // -------- layers --------
  for (int l = 0; l < NLC; l++){
    const float* be1l = be1 + l*HD;
    const float* be2l = be2 + l*HD;
    const float* bn1l = bn1 + l*HD;
    const float* bn2l = bn2 + l*HD;
    const __nv_bfloat16* Wt1h  = pWt1hi + (size_t)l*HD*KP2;
    const __nv_bfloat16* Wt1l_ = pWt1lo + (size_t)l*HD*KP2;
    const __nv_bfloat16* Wt2h  = pWt2hi + (size_t)l*HD*HD;
    const __nv_bfloat16* Wt2l_ = pWt2lo + (size_t)l*HD*HD;
    const __nv_bfloat16* Wsdh  = pWsdhi + (size_t)l*1024*HD;
    const __nv_bfloat16* Wsdl  = pWsdlo + (size_t)l*1024*HD;
    const __nv_bfloat16* W1h   = pWn1thi + (size_t)l*HD*2*HD;
    const __nv_bfloat16* W1l   = pWn1tlo + (size_t)l*HD*2*HD;
    const __nv_bfloat16* W2h   = pWn2thi + (size_t)l*HD*HD;
    const __nv_bfloat16* W2l   = pWn2tlo + (size_t)l*HD*HD;
    const float* gpl = pgp + (size_t)l*NBg*HD;

    k_ln<<<NN, 256>>>(ph, phn, phnhi, phnlo, ln_g + l*HD, ln_b + l*HD);
    // fused nps+npd (HMMA, fp32 out)
    hmma<2><<<dim3(8,10), blk, HMMA_SMEM>>>(phnhi, phnlo, Wsdh, Wsdl, HD, nullptr,
                                 nullptr,nullptr,nullptr,nullptr,nullptr,nullptr,
                                 nullptr,nullptr, pnps, pnpd);
    // edge MLP-1
    hmma<0><<<dim3(4,190), blk, HMMA_SMEM>>>(pAhi, pAlo, Wt1h, Wt1l_, KP2, be1l,
                                  pnps, pnpd, gpl, srcI, dstI, e2g, pe1hi, pe1lo, nullptr, nullptr);
    // edge MLP-2 + fused segment-sum
    k_zero<<<640, 256>>>(pagg, NN*HD);
    hmma<1><<<dim3(4,190), blk, HMMA_SMEM>>>(pe1hi, pe1lo, Wt2h, Wt2l_, HD, be2l,
                                  nullptr, nullptr, nullptr, srcI, nullptr, nullptr,
                                  nullptr, nullptr, pagg, nullptr);
    // node MLP (HMMA)
    k_ncat<<<NN, HD>>>();
    hmma<3><<<dim3(4,10), blk, HMMA_SMEM>>>(pncathi, pncatlo, W1h, W1l, 2*HD, bn1l,
                                 nullptr,nullptr,nullptr,nullptr,nullptr,nullptr,
                                 pt1hi, pt1lo, nullptr, nullptr);
    hmma<4><<<dim3(4,10), blk, HMMA_SMEM>>>(pt1hi, pt1lo, W2h, W2l, HD, bn2l,
                                 nullptr,nullptr,nullptr,nullptr,nullptr,nullptr,
                                 nullptr,nullptr, ph, nullptr);
  }

  // -------- heads --------
  k_ln<<<NN, 256>>>(ph, phn, phnhi, phnlo, fg, fb);
  k_zero<<<128, 256>>>(psum, NBg*HD);
  k_pool<<<NN, HD>>>(n2g);
  k_pos<<<NN, 96>>>(Wc, out);
  k_cell<<<NBg, 192>>>(na, Wlo, blo, out);
}

// round 14
// speedup vs baseline: 1.1623x; 1.1623x over previous
#include <cuda_runtime.h>
#include <cuda_bf16.h>
#include <math.h>
#include <stdint.h>

#define NBg  64
#define NPGC 20
#define HD   512
#define TDC  256
#define NFC  128
#define NLC  6
#define AC   100
#define NN   1280
#define EE   24320
#define KP2  832       /* 3 + 768 padded to 26*32 */
#define TWO_PI_F 6.283185307179586f

// ---------------- scratch ----------------
__device__ __nv_bfloat16 g_Ahi[(size_t)EE * KP2];
__device__ __nv_bfloat16 g_Alo[(size_t)EE * KP2];
__device__ __nv_bfloat16 g_e1hi[(size_t)EE * HD];
__device__ __nv_bfloat16 g_e1lo[(size_t)EE * HD];
__device__ __nv_bfloat16 g_Wt1hi[(size_t)NLC * HD * KP2];
__device__ __nv_bfloat16 g_Wt1lo[(size_t)NLC * HD * KP2];
__device__ __nv_bfloat16 g_Wt2hi[(size_t)NLC * HD * HD];
__device__ __nv_bfloat16 g_Wt2lo[(size_t)NLC * HD * HD];
__device__ __nv_bfloat16 g_Wsdhi[(size_t)NLC * 1024 * HD];   // [src(512) ; dst(512)] rows
__device__ __nv_bfloat16 g_Wsdlo[(size_t)NLC * 1024 * HD];
__device__ __nv_bfloat16 g_Wn1thi[(size_t)NLC * HD * 2 * HD];
__device__ __nv_bfloat16 g_Wn1tlo[(size_t)NLC * HD * 2 * HD];
__device__ __nv_bfloat16 g_Wn2thi[(size_t)NLC * HD * HD];
__device__ __nv_bfloat16 g_Wn2tlo[(size_t)NLC * HD * HD];
__device__ __nv_bfloat16 g_hnhi[NN * HD];
__device__ __nv_bfloat16 g_hnlo[NN * HD];
__device__ __nv_bfloat16 g_ncathi[NN * 2 * HD];
__device__ __nv_bfloat16 g_ncatlo[NN * 2 * HD];
__device__ __nv_bfloat16 g_t1hi[NN * HD];
__device__ __nv_bfloat16 g_t1lo[NN * HD];
__device__ float g_h[NN * HD];
__device__ float g_hn[NN * HD];
__device__ float g_nps[NN * HD];
__device__ float g_npd[NN * HD];
__device__ float g_agg[NN * HD];
__device__ float g_gp[(size_t)NLC * NBg * HD];
__device__ float g_ltl[NBg * 9];
__device__ float g_counts[NN];
__device__ float g_sum[NBg * HD];
__device__ float g_nodeproj[AC * HD];
__device__ float g_sj[HD];

__device__ __forceinline__ float siluf(float x){ return x / (1.f + expf(-x)); }

#define MMA16816(c, a, b0_, b1_) \
    asm volatile("mma.sync.aligned.m16n8k16.row.col.f32.bf16.bf16.f32 " \
        "{%0,%1,%2,%3}, {%4,%5,%6,%7}, {%8,%9}, {%0,%1,%2,%3};" \
        : "+f"((c)[0]), "+f"((c)[1]), "+f"((c)[2]), "+f"((c)[3]) \
        : "r"((a)[0]), "r"((a)[1]), "r"((a)[2]), "r"((a)[3]), "r"(b0_), "r"(b1_))

// ---------------- small kernels ----------------
__global__ void k_zero(float* p, int n){
  for (int i = blockIdx.x*blockDim.x + threadIdx.x; i < n; i += gridDim.x*blockDim.x) p[i] = 0.f;
}

__global__ void k_graphprep(const float* __restrict__ lp){
  int g = blockIdx.x*blockDim.x + threadIdx.x;
  if (g >= NBg) return;
  const float LM0=1.575442910194397f, LM1=1.7017393112182617f, LM2=1.9781638383865356f;
  const float LS0=0.24437622725963593f, LS1=0.26526379585266113f, LS2=0.3535512685775757f;
  float l0 = expf(lp[g*6+0]*LS0+LM0);
  float l1 = expf(lp[g*6+1]*LS1+LM1);
  float l2 = expf(lp[g*6+2]*LS2+LM2);
  float ang[3];
  #pragma unroll
  for (int i=0;i<3;i++){
    float x = lp[g*6+3+i];
    float sg = 1.f/(1.f+expf(-x));
    ang[i] = (59.9f + 60.2f*sg) * 0.017453292519943295f;
  }
  float c0=cosf(ang[0]), c1=cosf(ang[1]), c2=cosf(ang[2]);
  float s0=sinf(ang[0]), s1=sinf(ang[1]);
  float val = (c0*c1 - c2)/(s0*s1);
  val = fminf(1.f, fmaxf(-1.f, val));
  float gs = acosf(val);
  float L[3][3];
  L[0][0]=l0*s1;            L[0][1]=0.f;             L[0][2]=l0*c1;
  L[1][0]=-l1*s0*cosf(gs);  L[1][1]=l1*s0*sinf(gs);  L[1][2]=l1*c0;
  L[2][0]=0.f;              L[2][1]=0.f;             L[2][2]=l2;
  #pragma unroll
  for (int i=0;i<3;i++)
    #pragma unroll
    for (int k=0;k<3;k++)
      g_ltl[g*9+i*3+k] = L[i][0]*L[k][0] + L[i][1]*L[k][1] + L[i][2]*L[k][2];
}

__global__ void k_sj(const float* __restrict__ Wt, const float* __restrict__ Wlat){
  int j = blockIdx.x*64 + threadIdx.x;
  float acc = 0.f;
  for (int k=0;k<TDC;k++) acc += Wt[k]*Wlat[(size_t)(512+k)*HD + j];
  g_sj[j] = acc;
}

__global__ void k_nodeproj(const float* __restrict__ Wn, const float* __restrict__ Wlat){
  int a = blockIdx.x, j = threadIdx.x;
  float acc = 0.f;
  for (int k=0;k<HD;k++) acc += Wn[a*HD+k]*Wlat[(size_t)k*HD + j];
  g_nodeproj[a*HD+j] = acc;
}

__global__ void k_hinit(const int* __restrict__ at, const int* __restrict__ n2g,
                        const float* __restrict__ t){
  int n = blockIdx.x, j = threadIdx.x;
  int a = at[n]-1; if (a < 0) a = 0;
  g_h[n*HD+j] = g_nodeproj[a*HD+j] + t[n2g[n]] * g_sj[j];
}

__device__ __forceinline__ void split_store(__nv_bfloat16* hi, __nv_bfloat16* lo, size_t idx, float v){
  __nv_bfloat16 h = __float2bfloat16(v);
  hi[idx] = h;
  lo[idx] = __float2bfloat16(v - __bfloat162float(h));
}

__global__ void k_edgeprep(const float* __restrict__ fc, const int* __restrict__ srcI,
                           const int* __restrict__ dstI, const int* __restrict__ e2gI){
  int e = blockIdx.x; int tid = threadIdx.x;  // 128 threads
  int s = srcI[e], d = dstI[e], g = e2gI[e];
  float fd[3];
  #pragma unroll
  for (int i=0;i<3;i++){
    float z = TWO_PI_F * (fc[d*3+i] - fc[s*3+i]);
    fd[i] = atan2f(sinf(z), cosf(z)) / TWO_PI_F;
  }
  size_t rb = (size_t)e*KP2;
  if (tid == 0){
    float dots[3]; float nrm = 0.f;
    #pragma unroll
    for (int i=0;i<3;i++){
      float acc = 0.f;
      #pragma unroll
      for (int j=0;j<3;j++) acc += g_ltl[g*9+i*3+j]*fd[j];
      dots[i] = acc; nrm += acc*acc;
    }
    nrm = sqrtf(nrm) + 1e-12f;
    #pragma unroll
    for (int i=0;i<3;i++) split_store(g_Ahi, g_Alo, rb+i, dots[i]/nrm);
    atomicAdd(&g_counts[s], 1.f);
  }
  if (tid >= 64 && tid < 64 + (KP2 - 771)){
    int c = 771 + tid - 64;
    g_Ahi[rb+c] = __float2bfloat16(0.f);
    g_Alo[rb+c] = __float2bfloat16(0.f);
  }
  for (int idx = tid; idx < 3*NFC; idx += blockDim.x){
    int i = idx >> 7, k = idx & 127;
    float arg = TWO_PI_F * (float)k * fd[i];
    float sv, cv; sincosf(arg, &sv, &cv);
    split_store(g_Ahi, g_Alo, rb + 3 + idx, sv);
    split_store(g_Ahi, g_Alo, rb + 3 + 384 + idx, cv);
  }
}

// ---- weight transposes/splits (N-major bf16 hi/lo), once per launch ----
__global__ void k_wt1(const float* __restrict__ We1){
  int b = blockIdx.x;                // NLC*HD blocks
  int l = b >> 9, n = b & 511;
  const float* W = We1 + (size_t)l*2313*HD;
  size_t ob = (size_t)b*KP2;
  for (int k = threadIdx.x; k < KP2; k += 256){
    float v = 0.f;
    if (k < 3) v = W[(size_t)k*HD + n];
    else if (k < 771) v = W[(size_t)(k+1030)*HD + n];
    split_store(g_Wt1hi, g_Wt1lo, ob + k, v);
  }
}
__global__ void k_wt2(const float* __restrict__ We2){
  int b = blockIdx.x;
  int l = b >> 9, n = b & 511;
  const float* W = We2 + (size_t)l*HD*HD;
  size_t ob = (size_t)b*HD;
  for (int k = threadIdx.x; k < HD; k += 256)
    split_store(g_Wt2hi, g_Wt2lo, ob + k, W[(size_t)k*HD + n]);
}
// We1 src/dst blocks combined: rows 0..511 = src (We1 rows 3..514 col n),
// rows 512..1023 = dst (We1 rows 515..1026 col n-512)
__global__ void k_wsd(const float* __restrict__ We1){
  int b = blockIdx.x;                // NLC*1024 blocks
  int l = b >> 10, n = b & 1023;
  const float* W = We1 + (size_t)l*2313*HD;
  int base = (n < 512) ? 3 : 515;
  int wcol = (n < 512) ? n : (n - 512);
  size_t ob = (size_t)b*HD;
  for (int k = threadIdx.x; k < HD; k += 256)
    split_store(g_Wsdhi, g_Wsdlo, ob + k, W[(size_t)(base + k)*HD + wcol]);
}

__global__ void k_wn1t(const float* __restrict__ Wn1){
  int b = blockIdx.x;                // NLC*HD blocks
  int l = b >> 9, n = b & 511;
  const float* W = Wn1 + (size_t)l*1024*HD;
  size_t ob = (size_t)b*1024;
  for (int k = threadIdx.x; k < 1024; k += 256)
    split_store(g_Wn1thi, g_Wn1tlo, ob + k, W[(size_t)k*HD + n]);
}
__global__ void k_wn2t(const float* __restrict__ Wn2){
  int b = blockIdx.x;
  int l = b >> 9, n = b & 511;
  const float* W = Wn2 + (size_t)l*HD*HD;
  size_t ob = (size_t)b*HD;
  for (int k = threadIdx.x; k < HD; k += 256)
    split_store(g_Wn2thi, g_Wn2tlo, ob + k, W[(size_t)k*HD + n]);
}

// LN -> fp32 y + bf16 hi/lo split
__global__ void k_ln(const float* __restrict__ x, float* __restrict__ y,
                     __nv_bfloat16* __restrict__ yhi, __nv_bfloat16* __restrict__ ylo,
                     const float* __restrict__ gamma, const float* __restrict__ beta){
  int n = blockIdx.x, t = threadIdx.x;  // 256
  float v0 = x[n*HD+t], v1 = x[n*HD+t+256];
  __shared__ float s1[256], s2[256];
  s1[t] = v0+v1; s2[t] = v0*v0 + v1*v1;
  __syncthreads();
  for (int o=128;o>0;o>>=1){
    if (t<o){ s1[t]+=s1[t+o]; s2[t]+=s2[t+o]; }
    __syncthreads();
  }
  float mu = s1[0] * (1.f/512.f);
  float var = s2[0] * (1.f/512.f) - mu*mu;
  float rs = rsqrtf(var + 1e-5f);
  float o0 = (v0-mu)*rs*gamma[t]     + beta[t];
  float o1 = (v1-mu)*rs*gamma[t+256] + beta[t+256];
  y[n*HD+t]     = o0;
  y[n*HD+t+256] = o1;
  split_store(yhi, ylo, (size_t)n*HD+t,     o0);
  split_store(yhi, ylo, (size_t)n*HD+t+256, o1);
}

// all-layer gp precompute: grid (NBg, NLC)
__global__ void k_gp_all(const float* __restrict__ lp, const int* __restrict__ na,
                         const float* __restrict__ We1, const float* __restrict__ Wna){
  int g = blockIdx.x, l = blockIdx.y, j = threadIdx.x;  // 512
  const float* We1l = We1 + (size_t)l*2313*HD;
  const float* Wnal = Wna + (size_t)l*AC*HD;
  float acc = 0.f;
  #pragma unroll
  for (int k=0;k<6;k++) acc += lp[g*6+k]*We1l[(size_t)(1027+k)*HD + j];
  int nr = na[g]-1; if (nr < 0) nr = 0;
  const float* wrow = Wnal + (size_t)nr*HD;
  for (int k=0;k<HD;k++) acc += wrow[k]*We1l[(size_t)(1801+k)*HD + j];
  g_gp[(size_t)l*NBg*HD + g*HD + j] = acc;
}

// ncat = [hn | agg/counts] as bf16 hi/lo
__global__ void k_ncat(){
  int n = blockIdx.x, j = threadIdx.x;  // 512
  float c = fmaxf(g_counts[n], 1.f);
  split_store(g_ncathi, g_ncatlo, (size_t)n*1024 + j,       g_hn[n*HD+j]);
  split_store(g_ncathi, g_ncatlo, (size_t)n*1024 + 512 + j, g_agg[n*HD+j] / c);
}

__global__ void k_pool(const int* __restrict__ n2g){
  int n = blockIdx.x, j = threadIdx.x;
  atomicAdd(&g_sum[n2g[n]*HD + j], g_hn[n*HD+j]);
}

__global__ void k_pos(const float* __restrict__ Wc, float* __restrict__ out){
  int n = blockIdx.x; int w = threadIdx.x >> 5; int lane = threadIdx.x & 31;
  float acc = 0.f;
  for (int j=lane;j<HD;j+=32) acc += g_hn[n*HD+j]*Wc[j*3+w];
  #pragma unroll
  for (int o=16;o;o>>=1) acc += __shfl_down_sync(0xffffffffu, acc, o);
  if (lane==0) out[n*3+w] = acc;
}

__global__ void k_cell(const int* __restrict__ na, const float* __restrict__ Wlo,
                       const float* __restrict__ blo, float* __restrict__ out){
  int g = blockIdx.x; int o = threadIdx.x >> 5; int lane = threadIdx.x & 31;
  if (o >= 6) return;
  float nav = (float)na[g];
  float acc = 0.f;
  for (int j=lane;j<HD;j+=32){
    float s = g_sum[g*HD+j];
    acc += s*(Wlo[j*6+o]/nav + Wlo[(size_t)(HD+j)*6+o]);
  }
  #pragma unroll
  for (int off=16;off;off>>=1) acc += __shfl_down_sync(0xffffffffu, acc, off);
  if (lane==0) out[NN*3 + g*6 + o] = acc + blo[o];
}

// ---------------- HMMA GEMM: block 128x128, k-step 32, bf16 3-term split ----
// Single-buffer static smem, register prefetch (R12-proven structure).
// MODE 0: e1 = silu(acc + bias + nps[src]+npd[dst]+gp[e2g]) -> bf16 hi/lo (edge MLP-1)
// MODE 1: atomicAdd(agg[src], silu(acc + bias))                       (edge MLP-2)
// MODE 2: fp32 plain store; cols<512 -> fC, cols>=512 -> fC2          (nps+npd fused)
// MODE 3: silu(acc + bias) -> bf16 hi/lo                               (node t1)
// MODE 4: fC += silu(acc + bias) (fp32 residual)                       (node h)
#define SAS 40   /* smem row stride in bf16 (32 + 8 pad) */
template<int MODE>
__global__ void __launch_bounds__(256)
hmma(const __nv_bfloat16* __restrict__ Ahi, const __nv_bfloat16* __restrict__ Alo,
     const __nv_bfloat16* __restrict__ Bhi, const __nv_bfloat16* __restrict__ Blo,
     int KT,
     const float* __restrict__ bias,
     const float* __restrict__ nps, const float* __restrict__ npd, const float* __restrict__ gp,
     const int* __restrict__ srcI, const int* __restrict__ dstI, const int* __restrict__ e2gI,
     __nv_bfloat16* __restrict__ outhi, __nv_bfloat16* __restrict__ outlo,
     float* __restrict__ fC, float* __restrict__ fC2)
{
  __shared__ __align__(16) __nv_bfloat16 sAh[128][SAS];
  __shared__ __align__(16) __nv_bfloat16 sAl[128][SAS];
  __shared__ __align__(16) __nv_bfloat16 sBh[128][SAS];
  __shared__ __align__(16) __nv_bfloat16 sBl[128][SAS];

  int tid = threadIdx.x, wid = tid >> 5, lane = tid & 31;
  int warp_m = wid & 3, warp_n = wid >> 2;     // 4 x 2 warp grid
  int rowBlock = blockIdx.y * 128;
  int colBlock = blockIdx.x * 128;

  float acc[2][8][4];
  #pragma unroll
  for (int i=0;i<2;i++)
    #pragma unroll
    for (int j=0;j<8;j++)
      #pragma unroll
      for (int q=0;q<4;q++) acc[i][j][q] = 0.f;

  // gmem load mapping: thread -> (row = tid>>1, 16-bf16 half = tid&1), 2 uint4 each
  int lrow = tid >> 1, lcol = (tid & 1) * 16;
  const __nv_bfloat16* gAh = Ahi + (size_t)(rowBlock + lrow)*KT + lcol;
  const __nv_bfloat16* gAl = Alo + (size_t)(rowBlock + lrow)*KT + lcol;
  const __nv_bfloat16* gBh = Bhi + (size_t)(colBlock + lrow)*KT + lcol;
  const __nv_bfloat16* gBl = Blo + (size_t)(colBlock + lrow)*KT + lcol;

  int frow = lane >> 2;          // 0..7
  int fk   = (lane & 3) * 2;     // 0,2,4,6

  const int nsteps = KT >> 5;

  // prefetch step 0
  uint4 a0 = *(const uint4*)(gAh);
  uint4 a1 = *(const uint4*)(gAh + 8);
  uint4 a2 = *(const uint4*)(gAl);
  uint4 a3 = *(const uint4*)(gAl + 8);
  uint4 b0 = *(const uint4*)(gBh);
  uint4 b1 = *(const uint4*)(gBh + 8);
  uint4 b2 = *(const uint4*)(gBl);
  uint4 b3 = *(const uint4*)(gBl + 8);

  for (int s = 0; s < nsteps; s++){
    *(uint4*)&sAh[lrow][lcol]     = a0;
    *(uint4*)&sAh[lrow][lcol + 8] = a1;
    *(uint4*)&sAl[lrow][lcol]     = a2;
    *(uint4*)&sAl[lrow][lcol + 8] = a3;
    *(uint4*)&sBh[lrow][lcol]     = b0;
    *(uint4*)&sBh[lrow][lcol + 8] = b1;
    *(uint4*)&sBl[lrow][lcol]     = b2;
    *(uint4*)&sBl[lrow][lcol + 8] = b3;
    __syncthreads();

    if (s + 1 < nsteps){
      int o = (s+1)*32;
      a0 = *(const uint4*)(gAh + o);
      a1 = *(const uint4*)(gAh + o + 8);
      a2 = *(const uint4*)(gAl + o);
      a3 = *(const uint4*)(gAl + o + 8);
      b0 = *(const uint4*)(gBh + o);
      b1 = *(const uint4*)(gBh + o + 8);
      b2 = *(const uint4*)(gBl + o);
      b3 = *(const uint4*)(gBl + o + 8);
    }

    #pragma unroll
    for (int kk = 0; kk < 32; kk += 16){
      uint32_t ah[2][4], al[2][4];
      #pragma unroll
      for (int mt = 0; mt < 2; mt++){
        int abase = warp_m*32 + mt*16 + frow;
        #pragma unroll
        for (int j = 0; j < 4; j++){
          int row = abase + (j & 1)*8;
          int kc  = kk + fk + (j >> 1)*8;
          ah[mt][j] = *(const uint32_t*)&sAh[row][kc];
          al[mt][j] = *(const uint32_t*)&sAl[row][kc];
        }
      }
      #pragma unroll
      for (int nt = 0; nt < 8; nt++){
        int nrow = warp_n*64 + nt*8 + frow;
        uint32_t bh0 = *(const uint32_t*)&sBh[nrow][kk + fk];
        uint32_t bh1 = *(const uint32_t*)&sBh[nrow][kk + fk + 8];
        uint32_t bl0 = *(const uint32_t*)&sBl[nrow][kk + fk];
        uint32_t bl1 = *(const uint32_t*)&sBl[nrow][kk + fk + 8];
        #pragma unroll
        for (int mt = 0; mt < 2; mt++){
          MMA16816(acc[mt][nt], ah[mt], bh0, bh1);
          MMA16816(acc[mt][nt], ah[mt], bl0, bl1);
          MMA16816(acc[mt][nt], al[mt], bh0, bh1);
        }
      }
    }
    __syncthreads();
  }

  // ---- epilogue ----
  int cbase = colBlock + warp_n*64 + (lane & 3)*2;
  float2 bvv[8];
  if (MODE != 2){
    #pragma unroll
    for (int nt = 0; nt < 8; nt++) bvv[nt] = *(const float2*)(bias + cbase + nt*8);
  }

  #pragma unroll
  for (int mt = 0; mt < 2; mt++){
    #pragma unroll
    for (int h = 0; h < 2; h++){
      int r = rowBlock + warp_m*32 + mt*16 + (lane >> 2) + h*8;
      if (MODE == 0){
        int s2 = srcI[r], d2 = dstI[r], g2 = e2gI[r];
        const float* np_s = nps + (size_t)s2*HD;
        const float* np_d = npd + (size_t)d2*HD;
        const float* gpp  = gp  + (size_t)g2*HD;
        __nv_bfloat16* oh = outhi + (size_t)r*HD;
        __nv_bfloat16* ol = outlo + (size_t)r*HD;
        #pragma unroll
        for (int nt = 0; nt < 8; nt++){
          int c = cbase + nt*8;
          float2 sv = *(const float2*)(np_s + c);
          float2 dv = *(const float2*)(np_d + c);
          float2 gv = *(const float2*)(gpp + c);
          float v0 = siluf(acc[mt][nt][h*2+0] + bvv[nt].x + sv.x + dv.x + gv.x);
          float v1 = siluf(acc[mt][nt][h*2+1] + bvv[nt].y + sv.y + dv.y + gv.y);
          __nv_bfloat16 h0 = __float2bfloat16(v0);
          __nv_bfloat16 h1 = __float2bfloat16(v1);
          __nv_bfloat162 hip; hip.x = h0; hip.y = h1;
          __nv_bfloat162 lop;
          lop.x = __float2bfloat16(v0 - __bfloat162float(h0));
          lop.y = __float2bfloat16(v1 - __bfloat162float(h1));
          *(__nv_bfloat162*)(oh + c) = hip;
          *(__nv_bfloat162*)(ol + c) = lop;
        }
      } else if (MODE == 1){
        int s2 = srcI[r];
        float* ao = fC + (size_t)s2*HD;
        #pragma unroll
        for (int nt = 0; nt < 8; nt++){
          int c = cbase + nt*8;
          atomicAdd(ao + c,     siluf(acc[mt][nt][h*2+0] + bvv[nt].x));
          atomicAdd(ao + c + 1, siluf(acc[mt][nt][h*2+1] + bvv[nt].y));
        }
      } else if (MODE == 2){
        // fused nps/npd: cols < 512 -> fC, >= 512 -> fC2
        float* fo = (cbase < 512) ? (fC + (size_t)r*HD) : (fC2 + (size_t)r*HD - 512);
        #pragma unroll
        for (int nt = 0; nt < 8; nt++){
          int c = cbase + nt*8;
          fo[c]     = acc[mt][nt][h*2+0];
          fo[c + 1] = acc[mt][nt][h*2+1];
        }
      } else if (MODE == 3){
        __nv_bfloat16* oh = outhi + (size_t)r*HD;
        __nv_bfloat16* ol = outlo + (size_t)r*HD;
        #pragma unroll
        for (int nt = 0; nt < 8; nt++){
          int c = cbase + nt*8;
          float v0 = siluf(acc[mt][nt][h*2+0] + bvv[nt].x);
          float v1 = siluf(acc[mt][nt][h*2+1] + bvv[nt].y);
          __nv_bfloat16 h0 = __float2bfloat16(v0);
          __nv_bfloat16 h1 = __float2bfloat16(v1);
          __nv_bfloat162 hip; hip.x = h0; hip.y = h1;
          __nv_bfloat162 lop;
          lop.x = __float2bfloat16(v0 - __bfloat162float(h0));
          lop.y = __float2bfloat16(v1 - __bfloat162float(h1));
          *(__nv_bfloat162*)(oh + c) = hip;
          *(__nv_bfloat162*)(ol + c) = lop;
        }
      } else {  // MODE 4
        float* fo = fC + (size_t)r*HD;
        #pragma unroll
        for (int nt = 0; nt < 8; nt++){
          int c = cbase + nt*8;
          fo[c]     += siluf(acc[mt][nt][h*2+0] + bvv[nt].x);
          fo[c + 1] += siluf(acc[mt][nt][h*2+1] + bvv[nt].y);
        }
      }
    }
  }
}

// ---------------- host ----------------
extern "C" void kernel_launch(void* const* d_in, const int* in_sizes, int n_in,
                              void* d_out, int out_size) {
  const float* t    = (const float*)d_in[0];
  const float* fc   = (const float*)d_in[1];
  const float* lp   = (const float*)d_in[2];
  const int*   at   = (const int*)d_in[3];
  const int*   na   = (const int*)d_in[4];
  const int*   n2g  = (const int*)d_in[5];
  const int*   eidx = (const int*)d_in[6];
  const int*   e2g  = (const int*)d_in[7];
  const float* W_node   = (const float*)d_in[8];
  const float* W_time   = (const float*)d_in[9];
  const float* W_latent = (const float*)d_in[10];
  const float* ln_g = (const float*)d_in[11];
  const float* ln_b = (const float*)d_in[12];
  const float* We1  = (const float*)d_in[13];
  const float* be1  = (const float*)d_in[14];
  const float* We2  = (const float*)d_in[15];
  const float* be2  = (const float*)d_in[16];
  const float* Wn1  = (const float*)d_in[17];
  const float* bn1  = (const float*)d_in[18];
  const float* Wn2  = (const float*)d_in[19];
  const float* bn2  = (const float*)d_in[20];
  const float* Wna  = (const float*)d_in[21];
  const float* fg   = (const float*)d_in[22];
  const float* fb   = (const float*)d_in[23];
  const float* Wc   = (const float*)d_in[24];
  const float* Wlo  = (const float*)d_in[25];
  const float* blo  = (const float*)d_in[26];
  const int* srcI = eidx;
  const int* dstI = eidx + EE;
  float* out = (float*)d_out;

  float *ph,*phn,*pnps,*pnpd,*pagg,*pgp,*pcounts,*psum;
  __nv_bfloat16 *pAhi,*pAlo,*pe1hi,*pe1lo,*pWt1hi,*pWt1lo,*pWt2hi,*pWt2lo;
  __nv_bfloat16 *pWsdhi,*pWsdlo,*pWn1thi,*pWn1tlo,*pWn2thi,*pWn2tlo;
  __nv_bfloat16 *phnhi,*phnlo,*pncathi,*pncatlo,*pt1hi,*pt1lo;
  cudaGetSymbolAddress((void**)&ph, g_h);
  cudaGetSymbolAddress((void**)&phn, g_hn);
  cudaGetSymbolAddress((void**)&pnps, g_nps);
  cudaGetSymbolAddress((void**)&pnpd, g_npd);
  cudaGetSymbolAddress((void**)&pagg, g_agg);
  cudaGetSymbolAddress((void**)&pgp, g_gp);
  cudaGetSymbolAddress((void**)&pcounts, g_counts);
  cudaGetSymbolAddress((void**)&psum, g_sum);
  cudaGetSymbolAddress((void**)&pAhi, g_Ahi);
  cudaGetSymbolAddress((void**)&pAlo, g_Alo);
  cudaGetSymbolAddress((void**)&pe1hi, g_e1hi);
  cudaGetSymbolAddress((void**)&pe1lo, g_e1lo);
  cudaGetSymbolAddress((void**)&pWt1hi, g_Wt1hi);
  cudaGetSymbolAddress((void**)&pWt1lo, g_Wt1lo);
  cudaGetSymbolAddress((void**)&pWt2hi, g_Wt2hi);
  cudaGetSymbolAddress((void**)&pWt2lo, g_Wt2lo);
  cudaGetSymbolAddress((void**)&pWsdhi, g_Wsdhi);
  cudaGetSymbolAddress((void**)&pWsdlo, g_Wsdlo);
  cudaGetSymbolAddress((void**)&pWn1thi, g_Wn1thi);
  cudaGetSymbolAddress((void**)&pWn1tlo, g_Wn1tlo);
  cudaGetSymbolAddress((void**)&pWn2thi, g_Wn2thi);
  cudaGetSymbolAddress((void**)&pWn2tlo, g_Wn2tlo);
  cudaGetSymbolAddress((void**)&phnhi, g_hnhi);
  cudaGetSymbolAddress((void**)&phnlo, g_hnlo);
  cudaGetSymbolAddress((void**)&pncathi, g_ncathi);
  cudaGetSymbolAddress((void**)&pncatlo, g_ncatlo);
  cudaGetSymbolAddress((void**)&pt1hi, g_t1hi);
  cudaGetSymbolAddress((void**)&pt1lo, g_t1lo);

  dim3 blk(256);

  // -------- precompute --------
  k_graphprep<<<1, NBg>>>(lp);
  k_zero<<<8, 256>>>(pcounts, NN);
  k_edgeprep<<<EE, 128>>>(fc, srcI, dstI, e2g);
  k_wt1<<<NLC*HD, 256>>>(We1);
  k_wt2<<<NLC*HD, 256>>>(We2);
  k_wsd<<<NLC*1024, 256>>>(We1);
  k_wn1t<<<NLC*HD, 256>>>(Wn1);
  k_wn2t<<<NLC*HD, 256>>>(Wn2);
  k_gp_all<<<dim3(NBg, NLC), HD>>>(lp, na, We1, Wna);
  k_nodeproj<<<AC, HD>>>(W_node, W_latent);
  k_sj<<<8, 64>>>(W_time, W_latent);
  k_hinit<<<NN, HD>>>(at, n2g, t);

  // -------- layers --------
  for (int l = 0; l < NLC; l++){
    const float* be1l = be1 + l*HD;
    const float* be2l = be2 + l*HD;
    const float* bn1l = bn1 + l*HD;
    const float* bn2l = bn2 + l*HD;
    const __nv_bfloat16* Wt1h  = pWt1hi + (size_t)l*HD*KP2;
    const __nv_bfloat16* Wt1l_ = pWt1lo + (size_t)l*HD*KP2;
    const __nv_bfloat16* Wt2h  = pWt2hi + (size_t)l*HD*HD;
    const __nv_bfloat16* Wt2l_ = pWt2lo + (size_t)l*HD*HD;
    const __nv_bfloat16* Wsdh  = pWsdhi + (size_t)l*1024*HD;
    const __nv_bfloat16* Wsdl  = pWsdlo + (size_t)l*1024*HD;
    const __nv_bfloat16* W1h   = pWn1thi + (size_t)l*HD*2*HD;
    const __nv_bfloat16* W1l   = pWn1tlo + (size_t)l*HD*2*HD;
    const __nv_bfloat16* W2h   = pWn2thi + (size_t)l*HD*HD;
    const __nv_bfloat16* W2l   = pWn2tlo + (size_t)l*HD*HD;
    const float* gpl = pgp + (size_t)l*NBg*HD;

    k_ln<<<NN, 256>>>(ph, phn, phnhi, phnlo, ln_g + l*HD, ln_b + l*HD);
    // fused nps+npd (HMMA, fp32 out)
    hmma<2><<<dim3(8,10), blk>>>(phnhi, phnlo, Wsdh, Wsdl, HD, nullptr,
                                 nullptr,nullptr,nullptr,nullptr,nullptr,nullptr,
                                 nullptr,nullptr, pnps, pnpd);
    // edge MLP-1
    hmma<0><<<dim3(4,190), blk>>>(pAhi, pAlo, Wt1h, Wt1l_, KP2, be1l,
                                  pnps, pnpd, gpl, srcI, dstI, e2g, pe1hi, pe1lo, nullptr, nullptr);
    // edge MLP-2 + fused segment-sum
    k_zero<<<640, 256>>>(pagg, NN*HD);
    hmma<1><<<dim3(4,190), blk>>>(pe1hi, pe1lo, Wt2h, Wt2l_, HD, be2l,
                                  nullptr, nullptr, nullptr, srcI, nullptr, nullptr,
                                  nullptr, nullptr, pagg, nullptr);
    // node MLP (HMMA)
    k_ncat<<<NN, HD>>>();
    hmma<3><<<dim3(4,10), blk>>>(pncathi, pncatlo, W1h, W1l, 2*HD, bn1l,
                                 nullptr,nullptr,nullptr,nullptr,nullptr,nullptr,
                                 pt1hi, pt1lo, nullptr, nullptr);
    hmma<4><<<dim3(4,10), blk>>>(pt1hi, pt1lo, W2h, W2l, HD, bn2l,
                                 nullptr,nullptr,nullptr,nullptr,nullptr,nullptr,
                                 nullptr,nullptr, ph, nullptr);
  }

  // -------- heads --------
  k_ln<<<NN, 256>>>(ph, phn, phnhi, phnlo, fg, fb);
  k_zero<<<128, 256>>>(psum, NBg*HD);
  k_pool<<<NN, HD>>>(n2g);
  k_pos<<<NN, 96>>>(Wc, out);
  k_cell<<<NBg, 192>>>(na, Wlo, blo, out);
}

// round 15
// speedup vs baseline: 1.2008x; 1.0331x over previous
#include <cuda_runtime.h>
#include <cuda_bf16.h>
#include <math.h>
#include <stdint.h>

#define NBg  64
#define NPGC 20
#define HD   512
#define TDC  256
#define NFC  128
#define NLC  6
#define AC   100
#define NN   1280
#define EE   24320
#define KP2  832       /* 3 + 768 padded to 26*32 */
#define TWO_PI_F 6.283185307179586f

// ---------------- scratch ----------------
__device__ __nv_bfloat16 g_Ahi[(size_t)EE * KP2];
__device__ __nv_bfloat16 g_Alo[(size_t)EE * KP2];
__device__ __nv_bfloat16 g_e1hi[(size_t)EE * HD];
__device__ __nv_bfloat16 g_e1lo[(size_t)EE * HD];
__device__ __nv_bfloat16 g_Wt1hi[(size_t)NLC * HD * KP2];
__device__ __nv_bfloat16 g_Wt1lo[(size_t)NLC * HD * KP2];
__device__ __nv_bfloat16 g_Wt2hi[(size_t)NLC * HD * HD];
__device__ __nv_bfloat16 g_Wt2lo[(size_t)NLC * HD * HD];
__device__ __nv_bfloat16 g_Wsdhi[(size_t)NLC * 1024 * HD];   // [src(512) ; dst(512)] rows
__device__ __nv_bfloat16 g_Wsdlo[(size_t)NLC * 1024 * HD];
__device__ __nv_bfloat16 g_Wn1thi[(size_t)NLC * HD * 2 * HD];
__device__ __nv_bfloat16 g_Wn1tlo[(size_t)NLC * HD * 2 * HD];
__device__ __nv_bfloat16 g_Wn2thi[(size_t)NLC * HD * HD];
__device__ __nv_bfloat16 g_Wn2tlo[(size_t)NLC * HD * HD];
__device__ __nv_bfloat16 g_hnhi[NN * HD];
__device__ __nv_bfloat16 g_hnlo[NN * HD];
__device__ __nv_bfloat16 g_ncathi[NN * 2 * HD];
__device__ __nv_bfloat16 g_ncatlo[NN * 2 * HD];
__device__ __nv_bfloat16 g_t1hi[NN * HD];
__device__ __nv_bfloat16 g_t1lo[NN * HD];
__device__ float g_h[NN * HD];
__device__ float g_hn[NN * HD];
__device__ float g_nps[NN * HD];
__device__ float g_npd[NN * HD];
__device__ float g_agg[NN * HD];
__device__ float g_gp[(size_t)NLC * NBg * HD];
__device__ float g_ltl[NBg * 9];
__device__ float g_counts[NN];
__device__ float g_sum[NBg * HD];
__device__ float g_nodeproj[AC * HD];
__device__ float g_sj[HD];

__device__ __forceinline__ float siluf(float x){ return x / (1.f + expf(-x)); }

#define MMA16816(c, a, b0_, b1_) \
    asm volatile("mma.sync.aligned.m16n8k16.row.col.f32.bf16.bf16.f32 " \
        "{%0,%1,%2,%3}, {%4,%5,%6,%7}, {%8,%9}, {%0,%1,%2,%3};" \
        : "+f"((c)[0]), "+f"((c)[1]), "+f"((c)[2]), "+f"((c)[3]) \
        : "r"((a)[0]), "r"((a)[1]), "r"((a)[2]), "r"((a)[3]), "r"(b0_), "r"(b1_))

__device__ __forceinline__ uint32_t smem_to_u32(const void* p) {
    uint32_t a;
    asm("{ .reg .u64 tmp; cvta.to.shared.u64 tmp, %1; cvt.u32.u64 %0, tmp; }" : "=r"(a) : "l"(p));
    return a;
}
__device__ __forceinline__ void cpa16(uint32_t dst, const void* src){
  asm volatile("cp.async.cg.shared.global [%0], [%1], 16;" :: "r"(dst), "l"(src));
}
#define CP_COMMIT() asm volatile("cp.async.commit_group;" ::: "memory")
#define CP_WAIT(N)  asm volatile("cp.async.wait_group %0;" :: "n"(N) : "memory")

// ---------------- small kernels ----------------
__global__ void k_zero(float* p, int n){
  for (int i = blockIdx.x*blockDim.x + threadIdx.x; i < n; i += gridDim.x*blockDim.x) p[i] = 0.f;
}

__global__ void k_graphprep(const float* __restrict__ lp){
  int g = blockIdx.x*blockDim.x + threadIdx.x;
  if (g >= NBg) return;
  const float LM0=1.575442910194397f, LM1=1.7017393112182617f, LM2=1.9781638383865356f;
  const float LS0=0.24437622725963593f, LS1=0.26526379585266113f, LS2=0.3535512685775757f;
  float l0 = expf(lp[g*6+0]*LS0+LM0);
  float l1 = expf(lp[g*6+1]*LS1+LM1);
  float l2 = expf(lp[g*6+2]*LS2+LM2);
  float ang[3];
  #pragma unroll
  for (int i=0;i<3;i++){
    float x = lp[g*6+3+i];
    float sg = 1.f/(1.f+expf(-x));
    ang[i] = (59.9f + 60.2f*sg) * 0.017453292519943295f;
  }
  float c0=cosf(ang[0]), c1=cosf(ang[1]), c2=cosf(ang[2]);
  float s0=sinf(ang[0]), s1=sinf(ang[1]);
  float val = (c0*c1 - c2)/(s0*s1);
  val = fminf(1.f, fmaxf(-1.f, val));
  float gs = acosf(val);
  float L[3][3];
  L[0][0]=l0*s1;            L[0][1]=0.f;             L[0][2]=l0*c1;
  L[1][0]=-l1*s0*cosf(gs);  L[1][1]=l1*s0*sinf(gs);  L[1][2]=l1*c0;
  L[2][0]=0.f;              L[2][1]=0.f;             L[2][2]=l2;
  #pragma unroll
  for (int i=0;i<3;i++)
    #pragma unroll
    for (int k=0;k<3;k++)
      g_ltl[g*9+i*3+k] = L[i][0]*L[k][0] + L[i][1]*L[k][1] + L[i][2]*L[k][2];
}

__global__ void k_sj(const float* __restrict__ Wt, const float* __restrict__ Wlat){
  int j = blockIdx.x*64 + threadIdx.x;
  float acc = 0.f;
  for (int k=0;k<TDC;k++) acc += Wt[k]*Wlat[(size_t)(512+k)*HD + j];
  g_sj[j] = acc;
}

__global__ void k_nodeproj(const float* __restrict__ Wn, const float* __restrict__ Wlat){
  int a = blockIdx.x, j = threadIdx.x;
  float acc = 0.f;
  for (int k=0;k<HD;k++) acc += Wn[a*HD+k]*Wlat[(size_t)k*HD + j];
  g_nodeproj[a*HD+j] = acc;
}

__global__ void k_hinit(const int* __restrict__ at, const int* __restrict__ n2g,
                        const float* __restrict__ t){
  int n = blockIdx.x, j = threadIdx.x;
  int a = at[n]-1; if (a < 0) a = 0;
  g_h[n*HD+j] = g_nodeproj[a*HD+j] + t[n2g[n]] * g_sj[j];
}

__device__ __forceinline__ void split_store(__nv_bfloat16* hi, __nv_bfloat16* lo, size_t idx, float v){
  __nv_bfloat16 h = __float2bfloat16(v);
  hi[idx] = h;
  lo[idx] = __float2bfloat16(v - __bfloat162float(h));
}

__global__ void k_edgeprep(const float* __restrict__ fc, const int* __restrict__ srcI,
                           const int* __restrict__ dstI, const int* __restrict__ e2gI){
  int e = blockIdx.x; int tid = threadIdx.x;  // 128 threads
  int s = srcI[e], d = dstI[e], g = e2gI[e];
  float fd[3];
  #pragma unroll
  for (int i=0;i<3;i++){
    float z = TWO_PI_F * (fc[d*3+i] - fc[s*3+i]);
    fd[i] = atan2f(sinf(z), cosf(z)) / TWO_PI_F;
  }
  size_t rb = (size_t)e*KP2;
  if (tid == 0){
    float dots[3]; float nrm = 0.f;
    #pragma unroll
    for (int i=0;i<3;i++){
      float acc = 0.f;
      #pragma unroll
      for (int j=0;j<3;j++) acc += g_ltl[g*9+i*3+j]*fd[j];
      dots[i] = acc; nrm += acc*acc;
    }
    nrm = sqrtf(nrm) + 1e-12f;
    #pragma unroll
    for (int i=0;i<3;i++) split_store(g_Ahi, g_Alo, rb+i, dots[i]/nrm);
    atomicAdd(&g_counts[s], 1.f);
  }
  if (tid >= 64 && tid < 64 + (KP2 - 771)){
    int c = 771 + tid - 64;
    g_Ahi[rb+c] = __float2bfloat16(0.f);
    g_Alo[rb+c] = __float2bfloat16(0.f);
  }
  for (int idx = tid; idx < 3*NFC; idx += blockDim.x){
    int i = idx >> 7, k = idx & 127;
    float arg = TWO_PI_F * (float)k * fd[i];
    float sv, cv; sincosf(arg, &sv, &cv);
    split_store(g_Ahi, g_Alo, rb + 3 + idx, sv);
    split_store(g_Ahi, g_Alo, rb + 3 + 384 + idx, cv);
  }
}

// ---- weight transposes/splits (N-major bf16 hi/lo), once per launch ----
__global__ void k_wt1(const float* __restrict__ We1){
  int b = blockIdx.x;                // NLC*HD blocks
  int l = b >> 9, n = b & 511;
  const float* W = We1 + (size_t)l*2313*HD;
  size_t ob = (size_t)b*KP2;
  for (int k = threadIdx.x; k < KP2; k += 256){
    float v = 0.f;
    if (k < 3) v = W[(size_t)k*HD + n];
    else if (k < 771) v = W[(size_t)(k+1030)*HD + n];
    split_store(g_Wt1hi, g_Wt1lo, ob + k, v);
  }
}
__global__ void k_wt2(const float* __restrict__ We2){
  int b = blockIdx.x;
  int l = b >> 9, n = b & 511;
  const float* W = We2 + (size_t)l*HD*HD;
  size_t ob = (size_t)b*HD;
  for (int k = threadIdx.x; k < HD; k += 256)
    split_store(g_Wt2hi, g_Wt2lo, ob + k, W[(size_t)k*HD + n]);
}
// We1 src/dst blocks combined: rows 0..511 = src (We1 rows 3..514 col n),
// rows 512..1023 = dst (We1 rows 515..1026 col n-512)
__global__ void k_wsd(const float* __restrict__ We1){
  int b = blockIdx.x;                // NLC*1024 blocks
  int l = b >> 10, n = b & 1023;
  const float* W = We1 + (size_t)l*2313*HD;
  int base = (n < 512) ? 3 : 515;
  int wcol = (n < 512) ? n : (n - 512);
  size_t ob = (size_t)b*HD;
  for (int k = threadIdx.x; k < HD; k += 256)
    split_store(g_Wsdhi, g_Wsdlo, ob + k, W[(size_t)(base + k)*HD + wcol]);
}

__global__ void k_wn1t(const float* __restrict__ Wn1){
  int b = blockIdx.x;                // NLC*HD blocks
  int l = b >> 9, n = b & 511;
  const float* W = Wn1 + (size_t)l*1024*HD;
  size_t ob = (size_t)b*1024;
  for (int k = threadIdx.x; k < 1024; k += 256)
    split_store(g_Wn1thi, g_Wn1tlo, ob + k, W[(size_t)k*HD + n]);
}
__global__ void k_wn2t(const float* __restrict__ Wn2){
  int b = blockIdx.x;
  int l = b >> 9, n = b & 511;
  const float* W = Wn2 + (size_t)l*HD*HD;
  size_t ob = (size_t)b*HD;
  for (int k = threadIdx.x; k < HD; k += 256)
    split_store(g_Wn2thi, g_Wn2tlo, ob + k, W[(size_t)k*HD + n]);
}

// LN -> fp32 y + bf16 hi/lo split
__global__ void k_ln(const float* __restrict__ x, float* __restrict__ y,
                     __nv_bfloat16* __restrict__ yhi, __nv_bfloat16* __restrict__ ylo,
                     const float* __restrict__ gamma, const float* __restrict__ beta){
  int n = blockIdx.x, t = threadIdx.x;  // 256
  float v0 = x[n*HD+t], v1 = x[n*HD+t+256];
  __shared__ float s1[256], s2[256];
  s1[t] = v0+v1; s2[t] = v0*v0 + v1*v1;
  __syncthreads();
  for (int o=128;o>0;o>>=1){
    if (t<o){ s1[t]+=s1[t+o]; s2[t]+=s2[t+o]; }
    __syncthreads();
  }
  float mu = s1[0] * (1.f/512.f);
  float var = s2[0] * (1.f/512.f) - mu*mu;
  float rs = rsqrtf(var + 1e-5f);
  float o0 = (v0-mu)*rs*gamma[t]     + beta[t];
  float o1 = (v1-mu)*rs*gamma[t+256] + beta[t+256];
  y[n*HD+t]     = o0;
  y[n*HD+t+256] = o1;
  split_store(yhi, ylo, (size_t)n*HD+t,     o0);
  split_store(yhi, ylo, (size_t)n*HD+t+256, o1);
}

// all-layer gp precompute: grid (NBg, NLC)
__global__ void k_gp_all(const float* __restrict__ lp, const int* __restrict__ na,
                         const float* __restrict__ We1, const float* __restrict__ Wna){
  int g = blockIdx.x, l = blockIdx.y, j = threadIdx.x;  // 512
  const float* We1l = We1 + (size_t)l*2313*HD;
  const float* Wnal = Wna + (size_t)l*AC*HD;
  float acc = 0.f;
  #pragma unroll
  for (int k=0;k<6;k++) acc += lp[g*6+k]*We1l[(size_t)(1027+k)*HD + j];
  int nr = na[g]-1; if (nr < 0) nr = 0;
  const float* wrow = Wnal + (size_t)nr*HD;
  for (int k=0;k<HD;k++) acc += wrow[k]*We1l[(size_t)(1801+k)*HD + j];
  g_gp[(size_t)l*NBg*HD + g*HD + j] = acc;
}

// ncat = [hn | agg/counts] as bf16 hi/lo
__global__ void k_ncat(){
  int n = blockIdx.x, j = threadIdx.x;  // 512
  float c = fmaxf(g_counts[n], 1.f);
  split_store(g_ncathi, g_ncatlo, (size_t)n*1024 + j,       g_hn[n*HD+j]);
  split_store(g_ncathi, g_ncatlo, (size_t)n*1024 + 512 + j, g_agg[n*HD+j] / c);
}

__global__ void k_pool(const int* __restrict__ n2g){
  int n = blockIdx.x, j = threadIdx.x;
  atomicAdd(&g_sum[n2g[n]*HD + j], g_hn[n*HD+j]);
}

__global__ void k_pos(const float* __restrict__ Wc, float* __restrict__ out){
  int n = blockIdx.x; int w = threadIdx.x >> 5; int lane = threadIdx.x & 31;
  float acc = 0.f;
  for (int j=lane;j<HD;j+=32) acc += g_hn[n*HD+j]*Wc[j*3+w];
  #pragma unroll
  for (int o=16;o;o>>=1) acc += __shfl_down_sync(0xffffffffu, acc, o);
  if (lane==0) out[n*3+w] = acc;
}

__global__ void k_cell(const int* __restrict__ na, const float* __restrict__ Wlo,
                       const float* __restrict__ blo, float* __restrict__ out){
  int g = blockIdx.x; int o = threadIdx.x >> 5; int lane = threadIdx.x & 31;
  if (o >= 6) return;
  float nav = (float)na[g];
  float acc = 0.f;
  for (int j=lane;j<HD;j+=32){
    float s = g_sum[g*HD+j];
    acc += s*(Wlo[j*6+o]/nav + Wlo[(size_t)(HD+j)*6+o]);
  }
  #pragma unroll
  for (int off=16;off;off>>=1) acc += __shfl_down_sync(0xffffffffu, acc, off);
  if (lane==0) out[NN*3 + g*6 + o] = acc + blo[o];
}

// ---------------- HMMA GEMM: block 128x128, k-step 32, bf16 3-term split ----
// cp.async double-buffered pipeline (no prefetch registers -> 2 CTAs/SM).
// MODE 0: e1 = silu(acc + bias + nps[src]+npd[dst]+gp[e2g]) -> bf16 hi/lo (edge MLP-1)
// MODE 1: atomicAdd(agg[src], silu(acc + bias))                       (edge MLP-2)
// MODE 2: fp32 plain store; cols<512 -> fC, cols>=512 -> fC2          (nps+npd fused)
// MODE 3: silu(acc + bias) -> bf16 hi/lo                               (node t1)
// MODE 4: fC += silu(acc + bias) (fp32 residual)                       (node h)
#define SAS 40                      /* smem row stride in bf16 (32 + 8 pad) */
#define STG_ELEMS (128*SAS)         /* bf16 per array per stage */
#define STG_BYTES (4*STG_ELEMS*2)   /* 4 arrays per stage = 40960 B */
#define HMMA_SMEM (2*STG_BYTES)     /* 81920 B */
template<int MODE>
__global__ void __launch_bounds__(256,2)
hmma(const __nv_bfloat16* __restrict__ Ahi, const __nv_bfloat16* __restrict__ Alo,
     const __nv_bfloat16* __restrict__ Bhi, const __nv_bfloat16* __restrict__ Blo,
     int KT,
     const float* __restrict__ bias,
     const float* __restrict__ nps, const float* __restrict__ npd, const float* __restrict__ gp,
     const int* __restrict__ srcI, const int* __restrict__ dstI, const int* __restrict__ e2gI,
     __nv_bfloat16* __restrict__ outhi, __nv_bfloat16* __restrict__ outlo,
     float* __restrict__ fC, float* __restrict__ fC2)
{
  extern __shared__ __nv_bfloat16 dynsmem[];
  uint32_t smbase = smem_to_u32(dynsmem);

  int tid = threadIdx.x, wid = tid >> 5, lane = tid & 31;
  int warp_m = wid & 3, warp_n = wid >> 2;     // 4 x 2 warp grid
  int rowBlock = blockIdx.y * 128;
  int colBlock = blockIdx.x * 128;

  float acc[2][8][4];
  #pragma unroll
  for (int i=0;i<2;i++)
    #pragma unroll
    for (int j=0;j<8;j++)
      #pragma unroll
      for (int q=0;q<4;q++) acc[i][j][q] = 0.f;

  // gmem load mapping: thread -> (row = tid>>1, 16-bf16 half = tid&1), 2x cp.async 16B per array
  int lrow = tid >> 1, lcol = (tid & 1) * 16;
  const __nv_bfloat16* gAh = Ahi + (size_t)(rowBlock + lrow)*KT + lcol;
  const __nv_bfloat16* gAl = Alo + (size_t)(rowBlock + lrow)*KT + lcol;
  const __nv_bfloat16* gBh = Bhi + (size_t)(colBlock + lrow)*KT + lcol;
  const __nv_bfloat16* gBl = Blo + (size_t)(colBlock + lrow)*KT + lcol;

  int frow = lane >> 2;          // 0..7
  int fk   = (lane & 3) * 2;     // 0,2,4,6

  const int nsteps = KT >> 5;
  uint32_t sidx2 = (uint32_t)(lrow*SAS + lcol) * 2;   // byte offset within array

  // stage 0
  {
    uint32_t st = smbase;
    cpa16(st + 0*STG_ELEMS*2 + sidx2,      gAh);
    cpa16(st + 0*STG_ELEMS*2 + sidx2 + 16, gAh + 8);
    cpa16(st + 1*STG_ELEMS*2 + sidx2,      gAl);
    cpa16(st + 1*STG_ELEMS*2 + sidx2 + 16, gAl + 8);
    cpa16(st + 2*STG_ELEMS*2 + sidx2,      gBh);
    cpa16(st + 2*STG_ELEMS*2 + sidx2 + 16, gBh + 8);
    cpa16(st + 3*STG_ELEMS*2 + sidx2,      gBl);
    cpa16(st + 3*STG_ELEMS*2 + sidx2 + 16, gBl + 8);
    CP_COMMIT();
  }

  for (int s = 0; s < nsteps; s++){
    if (s + 1 < nsteps){
      int o = (s+1)*32;
      uint32_t st = smbase + ((s+1) & 1) * STG_BYTES;
      cpa16(st + 0*STG_ELEMS*2 + sidx2,      gAh + o);
      cpa16(st + 0*STG_ELEMS*2 + sidx2 + 16, gAh + o + 8);
      cpa16(st + 1*STG_ELEMS*2 + sidx2,      gAl + o);
      cpa16(st + 1*STG_ELEMS*2 + sidx2 + 16, gAl + o + 8);
      cpa16(st + 2*STG_ELEMS*2 + sidx2,      gBh + o);
      cpa16(st + 2*STG_ELEMS*2 + sidx2 + 16, gBh + o + 8);
      cpa16(st + 3*STG_ELEMS*2 + sidx2,      gBl + o);
      cpa16(st + 3*STG_ELEMS*2 + sidx2 + 16, gBl + o + 8);
      CP_COMMIT();
      CP_WAIT(1);     // stage s complete; s+1 may still be in flight
    } else {
      CP_WAIT(0);
    }
    __syncthreads();

    const __nv_bfloat16* cur = dynsmem + (s & 1) * (4*STG_ELEMS);
    const __nv_bfloat16* sAh = cur + 0*STG_ELEMS;
    const __nv_bfloat16* sAl = cur + 1*STG_ELEMS;
    const __nv_bfloat16* sBh = cur + 2*STG_ELEMS;
    const __nv_bfloat16* sBl = cur + 3*STG_ELEMS;

    #pragma unroll
    for (int kk = 0; kk < 32; kk += 16){
      uint32_t ah[2][4], al[2][4];
      #pragma unroll
      for (int mt = 0; mt < 2; mt++){
        int abase = warp_m*32 + mt*16 + frow;
        #pragma unroll
        for (int j = 0; j < 4; j++){
          int row = abase + (j & 1)*8;
          int kc  = kk + fk + (j >> 1)*8;
          ah[mt][j] = *(const uint32_t*)&sAh[row*SAS + kc];
          al[mt][j] = *(const uint32_t*)&sAl[row*SAS + kc];
        }
      }
      #pragma unroll
      for (int nt = 0; nt < 8; nt++){
        int nrow = warp_n*64 + nt*8 + frow;
        uint32_t bh0 = *(const uint32_t*)&sBh[nrow*SAS + kk + fk];
        uint32_t bh1 = *(const uint32_t*)&sBh[nrow*SAS + kk + fk + 8];
        uint32_t bl0 = *(const uint32_t*)&sBl[nrow*SAS + kk + fk];
        uint32_t bl1 = *(const uint32_t*)&sBl[nrow*SAS + kk + fk + 8];
        #pragma unroll
        for (int mt = 0; mt < 2; mt++){
          MMA16816(acc[mt][nt], ah[mt], bh0, bh1);
          MMA16816(acc[mt][nt], ah[mt], bl0, bl1);
          MMA16816(acc[mt][nt], al[mt], bh0, bh1);
        }
      }
    }
    __syncthreads();
  }

  // ---- epilogue ----
  int cbase = colBlock + warp_n*64 + (lane & 3)*2;
  float2 bvv[8];
  if (MODE != 2){
    #pragma unroll
    for (int nt = 0; nt < 8; nt++) bvv[nt] = *(const float2*)(bias + cbase + nt*8);
  }

  #pragma unroll
  for (int mt = 0; mt < 2; mt++){
    #pragma unroll
    for (int h = 0; h < 2; h++){
      int r = rowBlock + warp_m*32 + mt*16 + (lane >> 2) + h*8;
      if (MODE == 0){
        int s2 = srcI[r], d2 = dstI[r], g2 = e2gI[r];
        const float* np_s = nps + (size_t)s2*HD;
        const float* np_d = npd + (size_t)d2*HD;
        const float* gpp  = gp  + (size_t)g2*HD;
        __nv_bfloat16* oh = outhi + (size_t)r*HD;
        __nv_bfloat16* ol = outlo + (size_t)r*HD;
        #pragma unroll
        for (int nt = 0; nt < 8; nt++){
          int c = cbase + nt*8;
          float2 sv = *(const float2*)(np_s + c);
          float2 dv = *(const float2*)(np_d + c);
          float2 gv = *(const float2*)(gpp + c);
          float v0 = siluf(acc[mt][nt][h*2+0] + bvv[nt].x + sv.x + dv.x + gv.x);
          float v1 = siluf(acc[mt][nt][h*2+1] + bvv[nt].y + sv.y + dv.y + gv.y);
          __nv_bfloat16 h0 = __float2bfloat16(v0);
          __nv_bfloat16 h1 = __float2bfloat16(v1);
          __nv_bfloat162 hip; hip.x = h0; hip.y = h1;
          __nv_bfloat162 lop;
          lop.x = __float2bfloat16(v0 - __bfloat162float(h0));
          lop.y = __float2bfloat16(v1 - __bfloat162float(h1));
          *(__nv_bfloat162*)(oh + c) = hip;
          *(__nv_bfloat162*)(ol + c) = lop;
        }
      } else if (MODE == 1){
        int s2 = srcI[r];
        float* ao = fC + (size_t)s2*HD;
        #pragma unroll
        for (int nt = 0; nt < 8; nt++){
          int c = cbase + nt*8;
          atomicAdd(ao + c,     siluf(acc[mt][nt][h*2+0] + bvv[nt].x));
          atomicAdd(ao + c + 1, siluf(acc[mt][nt][h*2+1] + bvv[nt].y));
        }
      } else if (MODE == 2){
        // fused nps/npd: cols < 512 -> fC, >= 512 -> fC2
        float* fo = (cbase < 512) ? (fC + (size_t)r*HD) : (fC2 + (size_t)r*HD - 512);
        #pragma unroll
        for (int nt = 0; nt < 8; nt++){
          int c = cbase + nt*8;
          fo[c]     = acc[mt][nt][h*2+0];
          fo[c + 1] = acc[mt][nt][h*2+1];
        }
      } else if (MODE == 3){
        __nv_bfloat16* oh = outhi + (size_t)r*HD;
        __nv_bfloat16* ol = outlo + (size_t)r*HD;
        #pragma unroll
        for (int nt = 0; nt < 8; nt++){
          int c = cbase + nt*8;
          float v0 = siluf(acc[mt][nt][h*2+0] + bvv[nt].x);
          float v1 = siluf(acc[mt][nt][h*2+1] + bvv[nt].y);
          __nv_bfloat16 h0 = __float2bfloat16(v0);
          __nv_bfloat16 h1 = __float2bfloat16(v1);
          __nv_bfloat162 hip; hip.x = h0; hip.y = h1;
          __nv_bfloat162 lop;
          lop.x = __float2bfloat16(v0 - __bfloat162float(h0));
          lop.y = __float2bfloat16(v1 - __bfloat162float(h1));
          *(__nv_bfloat162*)(oh + c) = hip;
          *(__nv_bfloat162*)(ol + c) = lop;
        }
      } else {  // MODE 4
        float* fo = fC + (size_t)r*HD;
        #pragma unroll
        for (int nt = 0; nt < 8; nt++){
          int c = cbase + nt*8;
          fo[c]     += siluf(acc[mt][nt][h*2+0] + bvv[nt].x);
          fo[c + 1] += siluf(acc[mt][nt][h*2+1] + bvv[nt].y);
        }
      }
    }
  }
}

// ---------------- host ----------------
extern "C" void kernel_launch(void* const* d_in, const int* in_sizes, int n_in,
                              void* d_out, int out_size) {
  const float* t    = (const float*)d_in[0];
  const float* fc   = (const float*)d_in[1];
  const float* lp   = (const float*)d_in[2];
  const int*   at   = (const int*)d_in[3];
  const int*   na   = (const int*)d_in[4];
  const int*   n2g  = (const int*)d_in[5];
  const int*   eidx = (const int*)d_in[6];
  const int*   e2g  = (const int*)d_in[7];
  const float* W_node   = (const float*)d_in[8];
  const float* W_time   = (const float*)d_in[9];
  const float* W_latent = (const float*)d_in[10];
  const float* ln_g = (const float*)d_in[11];
  const float* ln_b = (const float*)d_in[12];
  const float* We1  = (const float*)d_in[13];
  const float* be1  = (const float*)d_in[14];
  const float* We2  = (const float*)d_in[15];
  const float* be2  = (const float*)d_in[16];
  const float* Wn1  = (const float*)d_in[17];
  const float* bn1  = (const float*)d_in[18];
  const float* Wn2  = (const float*)d_in[19];
  const float* bn2  = (const float*)d_in[20];
  const float* Wna  = (const float*)d_in[21];
  const float* fg   = (const float*)d_in[22];
  const float* fb   = (const float*)d_in[23];
  const float* Wc   = (const float*)d_in[24];
  const float* Wlo  = (const float*)d_in[25];
  const float* blo  = (const float*)d_in[26];
  const int* srcI = eidx;
  const int* dstI = eidx + EE;
  float* out = (float*)d_out;

  float *ph,*phn,*pnps,*pnpd,*pagg,*pgp,*pcounts,*psum;
  __nv_bfloat16 *pAhi,*pAlo,*pe1hi,*pe1lo,*pWt1hi,*pWt1lo,*pWt2hi,*pWt2lo;
  __nv_bfloat16 *pWsdhi,*pWsdlo,*pWn1thi,*pWn1tlo,*pWn2thi,*pWn2tlo;
  __nv_bfloat16 *phnhi,*phnlo,*pncathi,*pncatlo,*pt1hi,*pt1lo;
  cudaGetSymbolAddress((void**)&ph, g_h);
  cudaGetSymbolAddress((void**)&phn, g_hn);
  cudaGetSymbolAddress((void**)&pnps, g_nps);
  cudaGetSymbolAddress((void**)&pnpd, g_npd);
  cudaGetSymbolAddress((void**)&pagg, g_agg);
  cudaGetSymbolAddress((void**)&pgp, g_gp);
  cudaGetSymbolAddress((void**)&pcounts, g_counts);
  cudaGetSymbolAddress((void**)&psum, g_sum);
  cudaGetSymbolAddress((void**)&pAhi, g_Ahi);
  cudaGetSymbolAddress((void**)&pAlo, g_Alo);
  cudaGetSymbolAddress((void**)&pe1hi, g_e1hi);
  cudaGetSymbolAddress((void**)&pe1lo, g_e1lo);
  cudaGetSymbolAddress((void**)&pWt1hi, g_Wt1hi);
  cudaGetSymbolAddress((void**)&pWt1lo, g_Wt1lo);
  cudaGetSymbolAddress((void**)&pWt2hi, g_Wt2hi);
  cudaGetSymbolAddress((void**)&pWt2lo, g_Wt2lo);
  cudaGetSymbolAddress((void**)&pWsdhi, g_Wsdhi);
  cudaGetSymbolAddress((void**)&pWsdlo, g_Wsdlo);
  cudaGetSymbolAddress((void**)&pWn1thi, g_Wn1thi);
  cudaGetSymbolAddress((void**)&pWn1tlo, g_Wn1tlo);
  cudaGetSymbolAddress((void**)&pWn2thi, g_Wn2thi);
  cudaGetSymbolAddress((void**)&pWn2tlo, g_Wn2tlo);
  cudaGetSymbolAddress((void**)&phnhi, g_hnhi);
  cudaGetSymbolAddress((void**)&phnlo, g_hnlo);
  cudaGetSymbolAddress((void**)&pncathi, g_ncathi);
  cudaGetSymbolAddress((void**)&pncatlo, g_ncatlo);
  cudaGetSymbolAddress((void**)&pt1hi, g_t1hi);
  cudaGetSymbolAddress((void**)&pt1lo, g_t1lo);

  static bool attr_done = false;
  if (!attr_done){
    cudaFuncSetAttribute(hmma<0>, cudaFuncAttributeMaxDynamicSharedMemorySize, HMMA_SMEM);
    cudaFuncSetAttribute(hmma<1>, cudaFuncAttributeMaxDynamicSharedMemorySize, HMMA_SMEM);
    cudaFuncSetAttribute(hmma<2>, cudaFuncAttributeMaxDynamicSharedMemorySize, HMMA_SMEM);
    cudaFuncSetAttribute(hmma<3>, cudaFuncAttributeMaxDynamicSharedMemorySize, HMMA_SMEM);
    cudaFuncSetAttribute(hmma<4>, cudaFuncAttributeMaxDynamicSharedMemorySize, HMMA_SMEM);
    attr_done = true;
  }

  dim3 blk(256);

  // -------- precompute --------
  k_graphprep<<<1, NBg>>>(lp);
  k_zero<<<8, 256>>>(pcounts, NN);
  k_edgeprep<<<EE, 128>>>(fc, srcI, dstI, e2g);
  k_wt1<<<NLC*HD, 256>>>(We1);
  k_wt2<<<NLC*HD, 256>>>(We2);
  k_wsd<<<NLC*1024, 256>>>(We1);
  k_wn1t<<<NLC*HD, 256>>>(Wn1);
  k_wn2t<<<NLC*HD, 256>>>(Wn2);
  k_gp_all<<<dim3(NBg, NLC), HD>>>(lp, na, We1, Wna);
  k_nodeproj<<<AC, HD>>>(W_node, W_latent);
  k_sj<<<8, 64>>>(W_time, W_latent);
  k_hinit<<<NN, HD>>>(at, n2g, t);

  // -------- layers --------
  for (int l = 0; l < NLC; l++){
    const float* be1l = be1 + l*HD;
    const float* be2l = be2 + l*HD;
    const float* bn1l = bn1 + l*HD;
    const float* bn2l = bn2 + l*HD;
    const __nv_bfloat16* Wt1h  = pWt1hi + (size_t)l*HD*KP2;
    const __nv_bfloat16* Wt1l_ = pWt1lo + (size_t)l*HD*KP2;
    const __nv_bfloat16* Wt2h  = pWt2hi + (size_t)l*HD*HD;
    const __nv_bfloat16* Wt2l_ = pWt2lo + (size_t)l*HD*HD;
    const __nv_bfloat16* Wsdh  = pWsdhi + (size_t)l*1024*HD;
    const __nv_bfloat16* Wsdl  = pWsdlo + (size_t)l*1024*HD;
    const __nv_bfloat16* W1h   = pWn1thi + (size_t)l*HD*2*HD;
    const __nv_bfloat16* W1l   = pWn1tlo + (size_t)l*HD*2*HD;
    const __nv_bfloat16* W2h   = pWn2thi + (size_t)l*HD*HD;
    const __nv_bfloat16* W2l   = pWn2tlo + (size_t)l*HD*HD;
    const float* gpl = pgp + (size_t)l*NBg*HD;

    k_ln<<<NN, 256>>>(ph, phn, phnhi, phnlo, ln_g + l*HD, ln_b + l*HD);
    // fused nps+npd (HMMA, fp32 out)
    hmma<2><<<dim3(8,10), blk, HMMA_SMEM>>>(phnhi, phnlo, Wsdh, Wsdl, HD, nullptr,
                                 nullptr,nullptr,nullptr,nullptr,nullptr,nullptr,
                                 nullptr,nullptr, pnps, pnpd);
    // edge MLP-1
    hmma<0><<<dim3(4,190), blk, HMMA_SMEM>>>(pAhi, pAlo, Wt1h, Wt1l_, KP2, be1l,
                                  pnps, pnpd, gpl, srcI, dstI, e2g, pe1hi, pe1lo, nullptr, nullptr);
    // edge MLP-2 + fused segment-sum
    k_zero<<<640, 256>>>(pagg, NN*HD);
    hmma<1><<<dim3(4,190), blk, HMMA_SMEM>>>(pe1hi, pe1lo, Wt2h, Wt2l_, HD, be2l,
                                  nullptr, nullptr, nullptr, srcI, nullptr, nullptr,
                                  nullptr, nullptr, pagg, nullptr);
    // node MLP (HMMA)
    k_ncat<<<NN, HD>>>();
    hmma<3><<<dim3(4,10), blk, HMMA_SMEM>>>(pncathi, pncatlo, W1h, W1l, 2*HD, bn1l,
                                 nullptr,nullptr,nullptr,nullptr,nullptr,nullptr,
                                 pt1hi, pt1lo, nullptr, nullptr);
    hmma<4><<<dim3(4,10), blk, HMMA_SMEM>>>(pt1hi, pt1lo, W2h, W2l, HD, bn2l,
                                 nullptr,nullptr,nullptr,nullptr,nullptr,nullptr,
                                 nullptr,nullptr, ph, nullptr);
  }

  // -------- heads --------
  k_ln<<<NN, 256>>>(ph, phn, phnhi, phnlo, fg, fb);
  k_zero<<<128, 256>>>(psum, NBg*HD);
  k_pool<<<NN, HD>>>(n2g);
  k_pos<<<NN, 96>>>(Wc, out);
  k_cell<<<NBg, 192>>>(na, Wlo, blo, out);
}

// round 16
// speedup vs baseline: 1.3239x; 1.1025x over previous
#include <cuda_runtime.h>
#include <cuda_bf16.h>
#include <math.h>
#include <stdint.h>

#define NBg  64
#define NPGC 20
#define HD   512
#define TDC  256
#define NFC  128
#define NLC  6
#define AC   100
#define NN   1280
#define EE   24320
#define KP2  832       /* 3 + 768 padded to 26*32 */
#define TWO_PI_F 6.283185307179586f

// ---------------- scratch ----------------
__device__ __nv_bfloat16 g_Ahi[(size_t)EE * KP2];
__device__ __nv_bfloat16 g_Alo[(size_t)EE * KP2];
__device__ __nv_bfloat16 g_e1hi[(size_t)EE * HD];
__device__ __nv_bfloat16 g_e1lo[(size_t)EE * HD];
__device__ __nv_bfloat16 g_Wt1hi[(size_t)NLC * HD * KP2];
__device__ __nv_bfloat16 g_Wt1lo[(size_t)NLC * HD * KP2];
__device__ __nv_bfloat16 g_Wt2hi[(size_t)NLC * HD * HD];
__device__ __nv_bfloat16 g_Wt2lo[(size_t)NLC * HD * HD];
__device__ __nv_bfloat16 g_Wsdhi[(size_t)NLC * 1024 * HD];   // [src(512) ; dst(512)] rows
__device__ __nv_bfloat16 g_Wsdlo[(size_t)NLC * 1024 * HD];
__device__ __nv_bfloat16 g_Wn1thi[(size_t)NLC * HD * 2 * HD];
__device__ __nv_bfloat16 g_Wn1tlo[(size_t)NLC * HD * 2 * HD];
__device__ __nv_bfloat16 g_Wn2thi[(size_t)NLC * HD * HD];
__device__ __nv_bfloat16 g_Wn2tlo[(size_t)NLC * HD * HD];
__device__ __nv_bfloat16 g_hnhi[NN * HD];
__device__ __nv_bfloat16 g_hnlo[NN * HD];
__device__ __nv_bfloat16 g_ncathi[NN * 2 * HD];
__device__ __nv_bfloat16 g_ncatlo[NN * 2 * HD];
__device__ __nv_bfloat16 g_t1hi[NN * HD];
__device__ __nv_bfloat16 g_t1lo[NN * HD];
__device__ float g_h[NN * HD];
__device__ float g_hn[NN * HD];
__device__ float g_nps[NN * HD];
__device__ float g_npd[NN * HD];
__device__ float g_agg[NN * HD];
__device__ float g_gp[(size_t)NLC * NBg * HD];
__device__ float g_ltl[NBg * 9];
__device__ float g_counts[NN];
__device__ float g_sum[NBg * HD];
__device__ float g_nodeproj[AC * HD];
__device__ float g_sj[HD];

__device__ __forceinline__ float siluf(float x){ return x / (1.f + expf(-x)); }

#define MMA16816(c, a, b0_, b1_) \
    asm volatile("mma.sync.aligned.m16n8k16.row.col.f32.bf16.bf16.f32 " \
        "{%0,%1,%2,%3}, {%4,%5,%6,%7}, {%8,%9}, {%0,%1,%2,%3};" \
        : "+f"((c)[0]), "+f"((c)[1]), "+f"((c)[2]), "+f"((c)[3]) \
        : "r"((a)[0]), "r"((a)[1]), "r"((a)[2]), "r"((a)[3]), "r"(b0_), "r"(b1_))

#define LDSM_X4(r0,r1,r2,r3,addr) \
    asm volatile("ldmatrix.sync.aligned.m8n8.x4.shared.b16 {%0,%1,%2,%3}, [%4];" \
        : "=r"(r0),"=r"(r1),"=r"(r2),"=r"(r3) : "r"(addr))

__device__ __forceinline__ uint32_t smem_to_u32(const void* p) {
    uint32_t a;
    asm("{ .reg .u64 tmp; cvta.to.shared.u64 tmp, %1; cvt.u32.u64 %0, tmp; }" : "=r"(a) : "l"(p));
    return a;
}
__device__ __forceinline__ void cpa16(uint32_t dst, const void* src){
  asm volatile("cp.async.cg.shared.global [%0], [%1], 16;" :: "r"(dst), "l"(src));
}
#define CP_COMMIT() asm volatile("cp.async.commit_group;" ::: "memory")
#define CP_WAIT(N)  asm volatile("cp.async.wait_group %0;" :: "n"(N) : "memory")

// ---------------- small kernels ----------------
__global__ void k_zero(float* p, int n){
  for (int i = blockIdx.x*blockDim.x + threadIdx.x; i < n; i += gridDim.x*blockDim.x) p[i] = 0.f;
}

__global__ void k_graphprep(const float* __restrict__ lp){
  int g = blockIdx.x*blockDim.x + threadIdx.x;
  if (g >= NBg) return;
  const float LM0=1.575442910194397f, LM1=1.7017393112182617f, LM2=1.9781638383865356f;
  const float LS0=0.24437622725963593f, LS1=0.26526379585266113f, LS2=0.3535512685775757f;
  float l0 = expf(lp[g*6+0]*LS0+LM0);
  float l1 = expf(lp[g*6+1]*LS1+LM1);
  float l2 = expf(lp[g*6+2]*LS2+LM2);
  float ang[3];
  #pragma unroll
  for (int i=0;i<3;i++){
    float x = lp[g*6+3+i];
    float sg = 1.f/(1.f+expf(-x));
    ang[i] = (59.9f + 60.2f*sg) * 0.017453292519943295f;
  }
  float c0=cosf(ang[0]), c1=cosf(ang[1]), c2=cosf(ang[2]);
  float s0=sinf(ang[0]), s1=sinf(ang[1]);
  float val = (c0*c1 - c2)/(s0*s1);
  val = fminf(1.f, fmaxf(-1.f, val));
  float gs = acosf(val);
  float L[3][3];
  L[0][0]=l0*s1;            L[0][1]=0.f;             L[0][2]=l0*c1;
  L[1][0]=-l1*s0*cosf(gs);  L[1][1]=l1*s0*sinf(gs);  L[1][2]=l1*c0;
  L[2][0]=0.f;              L[2][1]=0.f;             L[2][2]=l2;
  #pragma unroll
  for (int i=0;i<3;i++)
    #pragma unroll
    for (int k=0;k<3;k++)
      g_ltl[g*9+i*3+k] = L[i][0]*L[k][0] + L[i][1]*L[k][1] + L[i][2]*L[k][2];
}

__global__ void k_sj(const float* __restrict__ Wt, const float* __restrict__ Wlat){
  int j = blockIdx.x*64 + threadIdx.x;
  float acc = 0.f;
  for (int k=0;k<TDC;k++) acc += Wt[k]*Wlat[(size_t)(512+k)*HD + j];
  g_sj[j] = acc;
}

__global__ void k_nodeproj(const float* __restrict__ Wn, const float* __restrict__ Wlat){
  int a = blockIdx.x, j = threadIdx.x;
  float acc = 0.f;
  for (int k=0;k<HD;k++) acc += Wn[a*HD+k]*Wlat[(size_t)k*HD + j];
  g_nodeproj[a*HD+j] = acc;
}

__global__ void k_hinit(const int* __restrict__ at, const int* __restrict__ n2g,
                        const float* __restrict__ t){
  int n = blockIdx.x, j = threadIdx.x;
  int a = at[n]-1; if (a < 0) a = 0;
  g_h[n*HD+j] = g_nodeproj[a*HD+j] + t[n2g[n]] * g_sj[j];
}

__device__ __forceinline__ void split_store(__nv_bfloat16* hi, __nv_bfloat16* lo, size_t idx, float v){
  __nv_bfloat16 h = __float2bfloat16(v);
  hi[idx] = h;
  lo[idx] = __float2bfloat16(v - __bfloat162float(h));
}

__global__ void k_edgeprep(const float* __restrict__ fc, const int* __restrict__ srcI,
                           const int* __restrict__ dstI, const int* __restrict__ e2gI){
  int e = blockIdx.x; int tid = threadIdx.x;  // 128 threads
  int s = srcI[e], d = dstI[e], g = e2gI[e];
  float fd[3];
  #pragma unroll
  for (int i=0;i<3;i++){
    float z = TWO_PI_F * (fc[d*3+i] - fc[s*3+i]);
    fd[i] = atan2f(sinf(z), cosf(z)) / TWO_PI_F;
  }
  size_t rb = (size_t)e*KP2;
  if (tid == 0){
    float dots[3]; float nrm = 0.f;
    #pragma unroll
    for (int i=0;i<3;i++){
      float acc = 0.f;
      #pragma unroll
      for (int j=0;j<3;j++) acc += g_ltl[g*9+i*3+j]*fd[j];
      dots[i] = acc; nrm += acc*acc;
    }
    nrm = sqrtf(nrm) + 1e-12f;
    #pragma unroll
    for (int i=0;i<3;i++) split_store(g_Ahi, g_Alo, rb+i, dots[i]/nrm);
    atomicAdd(&g_counts[s], 1.f);
  }
  if (tid >= 64 && tid < 64 + (KP2 - 771)){
    int c = 771 + tid - 64;
    g_Ahi[rb+c] = __float2bfloat16(0.f);
    g_Alo[rb+c] = __float2bfloat16(0.f);
  }
  for (int idx = tid; idx < 3*NFC; idx += blockDim.x){
    int i = idx >> 7, k = idx & 127;
    float arg = TWO_PI_F * (float)k * fd[i];
    float sv, cv; sincosf(arg, &sv, &cv);
    split_store(g_Ahi, g_Alo, rb + 3 + idx, sv);
    split_store(g_Ahi, g_Alo, rb + 3 + 384 + idx, cv);
  }
}

// ---- weight transposes/splits (N-major bf16 hi/lo), once per launch ----
__global__ void k_wt1(const float* __restrict__ We1){
  int b = blockIdx.x;                // NLC*HD blocks
  int l = b >> 9, n = b & 511;
  const float* W = We1 + (size_t)l*2313*HD;
  size_t ob = (size_t)b*KP2;
  for (int k = threadIdx.x; k < KP2; k += 256){
    float v = 0.f;
    if (k < 3) v = W[(size_t)k*HD + n];
    else if (k < 771) v = W[(size_t)(k+1030)*HD + n];
    split_store(g_Wt1hi, g_Wt1lo, ob + k, v);
  }
}
__global__ void k_wt2(const float* __restrict__ We2){
  int b = blockIdx.x;
  int l = b >> 9, n = b & 511;
  const float* W = We2 + (size_t)l*HD*HD;
  size_t ob = (size_t)b*HD;
  for (int k = threadIdx.x; k < HD; k += 256)
    split_store(g_Wt2hi, g_Wt2lo, ob + k, W[(size_t)k*HD + n]);
}
// We1 src/dst blocks combined
__global__ void k_wsd(const float* __restrict__ We1){
  int b = blockIdx.x;                // NLC*1024 blocks
  int l = b >> 10, n = b & 1023;
  const float* W = We1 + (size_t)l*2313*HD;
  int base = (n < 512) ? 3 : 515;
  int wcol = (n < 512) ? n : (n - 512);
  size_t ob = (size_t)b*HD;
  for (int k = threadIdx.x; k < HD; k += 256)
    split_store(g_Wsdhi, g_Wsdlo, ob + k, W[(size_t)(base + k)*HD + wcol]);
}

__global__ void k_wn1t(const float* __restrict__ Wn1){
  int b = blockIdx.x;                // NLC*HD blocks
  int l = b >> 9, n = b & 511;
  const float* W = Wn1 + (size_t)l*1024*HD;
  size_t ob = (size_t)b*1024;
  for (int k = threadIdx.x; k < 1024; k += 256)
    split_store(g_Wn1thi, g_Wn1tlo, ob + k, W[(size_t)k*HD + n]);
}
__global__ void k_wn2t(const float* __restrict__ Wn2){
  int b = blockIdx.x;
  int l = b >> 9, n = b & 511;
  const float* W = Wn2 + (size_t)l*HD*HD;
  size_t ob = (size_t)b*HD;
  for (int k = threadIdx.x; k < HD; k += 256)
    split_store(g_Wn2thi, g_Wn2tlo, ob + k, W[(size_t)k*HD + n]);
}

// LN -> fp32 y + bf16 hi/lo split
__global__ void k_ln(const float* __restrict__ x, float* __restrict__ y,
                     __nv_bfloat16* __restrict__ yhi, __nv_bfloat16* __restrict__ ylo,
                     const float* __restrict__ gamma, const float* __restrict__ beta){
  int n = blockIdx.x, t = threadIdx.x;  // 256
  float v0 = x[n*HD+t], v1 = x[n*HD+t+256];
  __shared__ float s1[256], s2[256];
  s1[t] = v0+v1; s2[t] = v0*v0 + v1*v1;
  __syncthreads();
  for (int o=128;o>0;o>>=1){
    if (t<o){ s1[t]+=s1[t+o]; s2[t]+=s2[t+o]; }
    __syncthreads();
  }
  float mu = s1[0] * (1.f/512.f);
  float var = s2[0] * (1.f/512.f) - mu*mu;
  float rs = rsqrtf(var + 1e-5f);
  float o0 = (v0-mu)*rs*gamma[t]     + beta[t];
  float o1 = (v1-mu)*rs*gamma[t+256] + beta[t+256];
  y[n*HD+t]     = o0;
  y[n*HD+t+256] = o1;
  split_store(yhi, ylo, (size_t)n*HD+t,     o0);
  split_store(yhi, ylo, (size_t)n*HD+t+256, o1);
}

// all-layer gp precompute: grid (NBg, NLC)
__global__ void k_gp_all(const float* __restrict__ lp, const int* __restrict__ na,
                         const float* __restrict__ We1, const float* __restrict__ Wna){
  int g = blockIdx.x, l = blockIdx.y, j = threadIdx.x;  // 512
  const float* We1l = We1 + (size_t)l*2313*HD;
  const float* Wnal = Wna + (size_t)l*AC*HD;
  float acc = 0.f;
  #pragma unroll
  for (int k=0;k<6;k++) acc += lp[g*6+k]*We1l[(size_t)(1027+k)*HD + j];
  int nr = na[g]-1; if (nr < 0) nr = 0;
  const float* wrow = Wnal + (size_t)nr*HD;
  for (int k=0;k<HD;k++) acc += wrow[k]*We1l[(size_t)(1801+k)*HD + j];
  g_gp[(size_t)l*NBg*HD + g*HD + j] = acc;
}

// ncat = [hn | agg/counts] as bf16 hi/lo
__global__ void k_ncat(){
  int n = blockIdx.x, j = threadIdx.x;  // 512
  float c = fmaxf(g_counts[n], 1.f);
  split_store(g_ncathi, g_ncatlo, (size_t)n*1024 + j,       g_hn[n*HD+j]);
  split_store(g_ncathi, g_ncatlo, (size_t)n*1024 + 512 + j, g_agg[n*HD+j] / c);
}

__global__ void k_pool(const int* __restrict__ n2g){
  int n = blockIdx.x, j = threadIdx.x;
  atomicAdd(&g_sum[n2g[n]*HD + j], g_hn[n*HD+j]);
}

__global__ void k_pos(const float* __restrict__ Wc, float* __restrict__ out){
  int n = blockIdx.x; int w = threadIdx.x >> 5; int lane = threadIdx.x & 31;
  float acc = 0.f;
  for (int j=lane;j<HD;j+=32) acc += g_hn[n*HD+j]*Wc[j*3+w];
  #pragma unroll
  for (int o=16;o;o>>=1) acc += __shfl_down_sync(0xffffffffu, acc, o);
  if (lane==0) out[n*3+w] = acc;
}

__global__ void k_cell(const int* __restrict__ na, const float* __restrict__ Wlo,
                       const float* __restrict__ blo, float* __restrict__ out){
  int g = blockIdx.x; int o = threadIdx.x >> 5; int lane = threadIdx.x & 31;
  if (o >= 6) return;
  float nav = (float)na[g];
  float acc = 0.f;
  for (int j=lane;j<HD;j+=32){
    float s = g_sum[g*HD+j];
    acc += s*(Wlo[j*6+o]/nav + Wlo[(size_t)(HD+j)*6+o]);
  }
  #pragma unroll
  for (int off=16;off;off>>=1) acc += __shfl_down_sync(0xffffffffu, acc, off);
  if (lane==0) out[NN*3 + g*6 + o] = acc + blo[o];
}

// ---------------- HMMA GEMM: block 128x128, k-step 32, bf16 3-term split ----
// cp.async double-buffered pipeline + ldmatrix fragment loads.
// MODE 0: e1 = silu(acc + bias + nps[src]+npd[dst]+gp[e2g]) -> bf16 hi/lo (edge MLP-1)
// MODE 1: atomicAdd(agg[src], silu(acc + bias))                       (edge MLP-2)
// MODE 2: fp32 plain store; cols<512 -> fC, cols>=512 -> fC2          (nps+npd fused)
// MODE 3: silu(acc + bias) -> bf16 hi/lo                               (node t1)
// MODE 4: fC += silu(acc + bias) (fp32 residual)                       (node h)
#define SAS 40                      /* smem row stride in bf16 (32 + 8 pad) */
#define STG_ELEMS (128*SAS)         /* bf16 per array per stage */
#define STG_BYTES (4*STG_ELEMS*2)   /* 4 arrays per stage = 40960 B */
#define HMMA_SMEM (2*STG_BYTES)     /* 81920 B */
template<int MODE>
__global__ void __launch_bounds__(256,2)
hmma(const __nv_bfloat16* __restrict__ Ahi, const __nv_bfloat16* __restrict__ Alo,
     const __nv_bfloat16* __restrict__ Bhi, const __nv_bfloat16* __restrict__ Blo,
     int KT,
     const float* __restrict__ bias,
     const float* __restrict__ nps, const float* __restrict__ npd, const float* __restrict__ gp,
     const int* __restrict__ srcI, const int* __restrict__ dstI, const int* __restrict__ e2gI,
     __nv_bfloat16* __restrict__ outhi, __nv_bfloat16* __restrict__ outlo,
     float* __restrict__ fC, float* __restrict__ fC2)
{
  extern __shared__ __nv_bfloat16 dynsmem[];
  uint32_t smbase = smem_to_u32(dynsmem);

  int tid = threadIdx.x, wid = tid >> 5, lane = tid & 31;
  int warp_m = wid & 3, warp_n = wid >> 2;     // 4 x 2 warp grid
  int rowBlock = blockIdx.y * 128;
  int colBlock = blockIdx.x * 128;

  float acc[2][8][4];
  #pragma unroll
  for (int i=0;i<2;i++)
    #pragma unroll
    for (int j=0;j<8;j++)
      #pragma unroll
      for (int q=0;q<4;q++) acc[i][j][q] = 0.f;

  // gmem load mapping: thread -> (row = tid>>1, 16-bf16 half = tid&1), 2x cp.async 16B per array
  int lrow = tid >> 1, lcol = (tid & 1) * 16;
  const __nv_bfloat16* gAh = Ahi + (size_t)(rowBlock + lrow)*KT + lcol;
  const __nv_bfloat16* gAl = Alo + (size_t)(rowBlock + lrow)*KT + lcol;
  const __nv_bfloat16* gBh = Bhi + (size_t)(colBlock + lrow)*KT + lcol;
  const __nv_bfloat16* gBl = Blo + (size_t)(colBlock + lrow)*KT + lcol;

  // ldmatrix lane offsets (bf16 units within array)
  // A (x4): lanes 0-15 -> rows 0-15 k0 ; lanes 16-31 -> rows 0-15 k8
  uint32_t a_off = ((uint32_t)(warp_m*32 + (lane & 15)) * SAS + (uint32_t)((lane >> 4) * 8)) * 2;
  // B (x4): lanes 0-7 n0-7 k0 ; 8-15 n0-7 k8 ; 16-23 n8-15 k0 ; 24-31 n8-15 k8
  uint32_t b_off = ((uint32_t)(warp_n*64 + ((lane >> 4) * 8) + (lane & 7)) * SAS
                    + (uint32_t)(((lane >> 3) & 1) * 8)) * 2;

  const int nsteps = KT >> 5;
  uint32_t sidx2 = (uint32_t)(lrow*SAS + lcol) * 2;   // byte offset within array

  // stage 0
  {
    uint32_t st = smbase;
    cpa16(st + 0*STG_ELEMS*2 + sidx2,      gAh);
    cpa16(st + 0*STG_ELEMS*2 + sidx2 + 16, gAh + 8);
    cpa16(st + 1*STG_ELEMS*2 + sidx2,      gAl);
    cpa16(st + 1*STG_ELEMS*2 + sidx2 + 16, gAl + 8);
    cpa16(st + 2*STG_ELEMS*2 + sidx2,      gBh);
    cpa16(st + 2*STG_ELEMS*2 + sidx2 + 16, gBh + 8);
    cpa16(st + 3*STG_ELEMS*2 + sidx2,      gBl);
    cpa16(st + 3*STG_ELEMS*2 + sidx2 + 16, gBl + 8);
    CP_COMMIT();
  }

  for (int s = 0; s < nsteps; s++){
    if (s + 1 < nsteps){
      int o = (s+1)*32;
      uint32_t st = smbase + ((s+1) & 1) * STG_BYTES;
      cpa16(st + 0*STG_ELEMS*2 + sidx2,      gAh + o);
      cpa16(st + 0*STG_ELEMS*2 + sidx2 + 16, gAh + o + 8);
      cpa16(st + 1*STG_ELEMS*2 + sidx2,      gAl + o);
      cpa16(st + 1*STG_ELEMS*2 + sidx2 + 16, gAl + o + 8);
      cpa16(st + 2*STG_ELEMS*2 + sidx2,      gBh + o);
      cpa16(st + 2*STG_ELEMS*2 + sidx2 + 16, gBh + o + 8);
      cpa16(st + 3*STG_ELEMS*2 + sidx2,      gBl + o);
      cpa16(st + 3*STG_ELEMS*2 + sidx2 + 16, gBl + o + 8);
      CP_COMMIT();
      CP_WAIT(1);     // stage s complete; s+1 may still be in flight
    } else {
      CP_WAIT(0);
    }
    __syncthreads();

    uint32_t cur = smbase + (s & 1) * STG_BYTES;
    uint32_t cAh = cur + 0*STG_ELEMS*2;
    uint32_t cAl = cur + 1*STG_ELEMS*2;
    uint32_t cBh = cur + 2*STG_ELEMS*2;
    uint32_t cBl = cur + 3*STG_ELEMS*2;

    #pragma unroll
    for (int kk = 0; kk < 32; kk += 16){
      uint32_t ah[2][4], al[2][4], bh[4][4], bl[4][4];
      #pragma unroll
      for (int mt = 0; mt < 2; mt++){
        uint32_t off = a_off + (uint32_t)(mt*16*SAS + kk)*2;
        LDSM_X4(ah[mt][0], ah[mt][1], ah[mt][2], ah[mt][3], cAh + off);
        LDSM_X4(al[mt][0], al[mt][1], al[mt][2], al[mt][3], cAl + off);
      }
      #pragma unroll
      for (int ng = 0; ng < 4; ng++){
        uint32_t off = b_off + (uint32_t)(ng*16*SAS + kk)*2;
        LDSM_X4(bh[ng][0], bh[ng][1], bh[ng][2], bh[ng][3], cBh + off);
        LDSM_X4(bl[ng][0], bl[ng][1], bl[ng][2], bl[ng][3], cBl + off);
      }
      #pragma unroll
      for (int nt = 0; nt < 8; nt++){
        int ng = nt >> 1, sel = (nt & 1) * 2;
        #pragma unroll
        for (int mt = 0; mt < 2; mt++){
          MMA16816(acc[mt][nt], ah[mt], bh[ng][sel], bh[ng][sel+1]);
          MMA16816(acc[mt][nt], ah[mt], bl[ng][sel], bl[ng][sel+1]);
          MMA16816(acc[mt][nt], al[mt], bh[ng][sel], bh[ng][sel+1]);
        }
      }
    }
    __syncthreads();
  }

  // ---- epilogue ----
  int cbase = colBlock + warp_n*64 + (lane & 3)*2;
  float2 bvv[8];
  if (MODE != 2){
    #pragma unroll
    for (int nt = 0; nt < 8; nt++) bvv[nt] = *(const float2*)(bias + cbase + nt*8);
  }

  #pragma unroll
  for (int mt = 0; mt < 2; mt++){
    #pragma unroll
    for (int h = 0; h < 2; h++){
      int r = rowBlock + warp_m*32 + mt*16 + (lane >> 2) + h*8;
      if (MODE == 0){
        int s2 = srcI[r], d2 = dstI[r], g2 = e2gI[r];
        const float* np_s = nps + (size_t)s2*HD;
        const float* np_d = npd + (size_t)d2*HD;
        const float* gpp  = gp  + (size_t)g2*HD;
        __nv_bfloat16* oh = outhi + (size_t)r*HD;
        __nv_bfloat16* ol = outlo + (size_t)r*HD;
        #pragma unroll
        for (int nt = 0; nt < 8; nt++){
          int c = cbase + nt*8;
          float2 sv = *(const float2*)(np_s + c);
          float2 dv = *(const float2*)(np_d + c);
          float2 gv = *(const float2*)(gpp + c);
          float v0 = siluf(acc[mt][nt][h*2+0] + bvv[nt].x + sv.x + dv.x + gv.x);
          float v1 = siluf(acc[mt][nt][h*2+1] + bvv[nt].y + sv.y + dv.y + gv.y);
          __nv_bfloat16 h0 = __float2bfloat16(v0);
          __nv_bfloat16 h1 = __float2bfloat16(v1);
          __nv_bfloat162 hip; hip.x = h0; hip.y = h1;
          __nv_bfloat162 lop;
          lop.x = __float2bfloat16(v0 - __bfloat162float(h0));
          lop.y = __float2bfloat16(v1 - __bfloat162float(h1));
          *(__nv_bfloat162*)(oh + c) = hip;
          *(__nv_bfloat162*)(ol + c) = lop;
        }
      } else if (MODE == 1){
        int s2 = srcI[r];
        float* ao = fC + (size_t)s2*HD;
        #pragma unroll
        for (int nt = 0; nt < 8; nt++){
          int c = cbase + nt*8;
          atomicAdd(ao + c,     siluf(acc[mt][nt][h*2+0] + bvv[nt].x));
          atomicAdd(ao + c + 1, siluf(acc[mt][nt][h*2+1] + bvv[nt].y));
        }
      } else if (MODE == 2){
        // fused nps/npd: cols < 512 -> fC, >= 512 -> fC2
        float* fo = (cbase < 512) ? (fC + (size_t)r*HD) : (fC2 + (size_t)r*HD - 512);
        #pragma unroll
        for (int nt = 0; nt < 8; nt++){
          int c = cbase + nt*8;
          fo[c]     = acc[mt][nt][h*2+0];
          fo[c + 1] = acc[mt][nt][h*2+1];
        }
      } else if (MODE == 3){
        __nv_bfloat16* oh = outhi + (size_t)r*HD;
        __nv_bfloat16* ol = outlo + (size_t)r*HD;
        #pragma unroll
        for (int nt = 0; nt < 8; nt++){
          int c = cbase + nt*8;
          float v0 = siluf(acc[mt][nt][h*2+0] + bvv[nt].x);
          float v1 = siluf(acc[mt][nt][h*2+1] + bvv[nt].y);
          __nv_bfloat16 h0 = __float2bfloat16(v0);
          __nv_bfloat16 h1 = __float2bfloat16(v1);
          __nv_bfloat162 hip; hip.x = h0; hip.y = h1;
          __nv_bfloat162 lop;
          lop.x = __float2bfloat16(v0 - __bfloat162float(h0));
          lop.y = __float2bfloat16(v1 - __bfloat162float(h1));
          *(__nv_bfloat162*)(oh + c) = hip;
          *(__nv_bfloat162*)(ol + c) = lop;
        }
      } else {  // MODE 4
        float* fo = fC + (size_t)r*HD;
        #pragma unroll
        for (int nt = 0; nt < 8; nt++){
          int c = cbase + nt*8;
          fo[c]     += siluf(acc[mt][nt][h*2+0] + bvv[nt].x);
          fo[c + 1] += siluf(acc[mt][nt][h*2+1] + bvv[nt].y);
        }
      }
    }
  }
}

// ---------------- host ----------------
extern "C" void kernel_launch(void* const* d_in, const int* in_sizes, int n_in,
                              void* d_out, int out_size) {
  const float* t    = (const float*)d_in[0];
  const float* fc   = (const float*)d_in[1];
  const float* lp   = (const float*)d_in[2];
  const int*   at   = (const int*)d_in[3];
  const int*   na   = (const int*)d_in[4];
  const int*   n2g  = (const int*)d_in[5];
  const int*   eidx = (const int*)d_in[6];
  const int*   e2g  = (const int*)d_in[7];
  const float* W_node   = (const float*)d_in[8];
  const float* W_time   = (const float*)d_in[9];
  const float* W_latent = (const float*)d_in[10];
  const float* ln_g = (const float*)d_in[11];
  const float* ln_b = (const float*)d_in[12];
  const float* We1  = (const float*)d_in[13];
  const float* be1  = (const float*)d_in[14];
  const float* We2  = (const float*)d_in[15];
  const float* be2  = (const float*)d_in[16];
  const float* Wn1  = (const float*)d_in[17];
  const float* bn1  = (const float*)d_in[18];
  const float* Wn2  = (const float*)d_in[19];
  const float* bn2  = (const float*)d_in[20];
  const float* Wna  = (const float*)d_in[21];
  const float* fg   = (const float*)d_in[22];
  const float* fb   = (const float*)d_in[23];
  const float* Wc   = (const float*)d_in[24];
  const float* Wlo  = (const float*)d_in[25];
  const float* blo  = (const float*)d_in[26];
  const int* srcI = eidx;
  const int* dstI = eidx + EE;
  float* out = (float*)d_out;

  float *ph,*phn,*pnps,*pnpd,*pagg,*pgp,*pcounts,*psum;
  __nv_bfloat16 *pAhi,*pAlo,*pe1hi,*pe1lo,*pWt1hi,*pWt1lo,*pWt2hi,*pWt2lo;
  __nv_bfloat16 *pWsdhi,*pWsdlo,*pWn1thi,*pWn1tlo,*pWn2thi,*pWn2tlo;
  __nv_bfloat16 *phnhi,*phnlo,*pncathi,*pncatlo,*pt1hi,*pt1lo;
  cudaGetSymbolAddress((void**)&ph, g_h);
  cudaGetSymbolAddress((void**)&phn, g_hn);
  cudaGetSymbolAddress((void**)&pnps, g_nps);
  cudaGetSymbolAddress((void**)&pnpd, g_npd);
  cudaGetSymbolAddress((void**)&pagg, g_agg);
  cudaGetSymbolAddress((void**)&pgp, g_gp);
  cudaGetSymbolAddress((void**)&pcounts, g_counts);
  cudaGetSymbolAddress((void**)&psum, g_sum);
  cudaGetSymbolAddress((void**)&pAhi, g_Ahi);
  cudaGetSymbolAddress((void**)&pAlo, g_Alo);
  cudaGetSymbolAddress((void**)&pe1hi, g_e1hi);
  cudaGetSymbolAddress((void**)&pe1lo, g_e1lo);
  cudaGetSymbolAddress((void**)&pWt1hi, g_Wt1hi);
  cudaGetSymbolAddress((void**)&pWt1lo, g_Wt1lo);
  cudaGetSymbolAddress((void**)&pWt2hi, g_Wt2hi);
  cudaGetSymbolAddress((void**)&pWt2lo, g_Wt2lo);
  cudaGetSymbolAddress((void**)&pWsdhi, g_Wsdhi);
  cudaGetSymbolAddress((void**)&pWsdlo, g_Wsdlo);
  cudaGetSymbolAddress((void**)&pWn1thi, g_Wn1thi);
  cudaGetSymbolAddress((void**)&pWn1tlo, g_Wn1tlo);
  cudaGetSymbolAddress((void**)&pWn2thi, g_Wn2thi);
  cudaGetSymbolAddress((void**)&pWn2tlo, g_Wn2tlo);
  cudaGetSymbolAddress((void**)&phnhi, g_hnhi);
  cudaGetSymbolAddress((void**)&phnlo, g_hnlo);
  cudaGetSymbolAddress((void**)&pncathi, g_ncathi);
  cudaGetSymbolAddress((void**)&pncatlo, g_ncatlo);
  cudaGetSymbolAddress((void**)&pt1hi, g_t1hi);
  cudaGetSymbolAddress((void**)&pt1lo, g_t1lo);

  static bool attr_done = false;
  if (!attr_done){
    cudaFuncSetAttribute(hmma<0>, cudaFuncAttributeMaxDynamicSharedMemorySize, HMMA_SMEM);
    cudaFuncSetAttribute(hmma<1>, cudaFuncAttributeMaxDynamicSharedMemorySize, HMMA_SMEM);
    cudaFuncSetAttribute(hmma<2>, cudaFuncAttributeMaxDynamicSharedMemorySize, HMMA_SMEM);
    cudaFuncSetAttribute(hmma<3>, cudaFuncAttributeMaxDynamicSharedMemorySize, HMMA_SMEM);
    cudaFuncSetAttribute(hmma<4>, cudaFuncAttributeMaxDynamicSharedMemorySize, HMMA_SMEM);
    attr_done = true;
  }

  dim3 blk(256);

  // -------- precompute --------
  k_graphprep<<<1, NBg>>>(lp);
  k_zero<<<8, 256>>>(pcounts, NN);
  k_edgeprep<<<EE, 128>>>(fc, srcI, dstI, e2g);
  k_wt1<<<NLC*HD, 256>>>(We1);
  k_wt2<<<NLC*HD, 256>>>(We2);
  k_wsd<<<NLC*1024, 256>>>(We1);
  k_wn1t<<<NLC*HD, 256>>>(Wn1);
  k_wn2t<<<NLC*HD, 256>>>(Wn2);
  k_gp_all<<<dim3(NBg, NLC), HD>>>(lp, na, We1, Wna);
  k_nodeproj<<<AC, HD>>>(W_node, W_latent);
  k_sj<<<8, 64>>>(W_time, W_latent);
  k_hinit<<<NN, HD>>>(at, n2g, t);

  // -------- layers --------
  for (int l = 0; l < NLC; l++){
    const float* be1l = be1 + l*HD;
    const float* be2l = be2 + l*HD;
    const float* bn1l = bn1 + l*HD;
    const float* bn2l = bn2 + l*HD;
    const __nv_bfloat16* Wt1h  = pWt1hi + (size_t)l*HD*KP2;
    const __nv_bfloat16* Wt1l_ = pWt1lo + (size_t)l*HD*KP2;
    const __nv_bfloat16* Wt2h  = pWt2hi + (size_t)l*HD*HD;
    const __nv_bfloat16* Wt2l_ = pWt2lo + (size_t)l*HD*HD;
    const __nv_bfloat16* Wsdh  = pWsdhi + (size_t)l*1024*HD;
    const __nv_bfloat16* Wsdl  = pWsdlo + (size_t)l*1024*HD;
    const __nv_bfloat16* W1h   = pWn1thi + (size_t)l*HD*2*HD;
    const __nv_bfloat16* W1l   = pWn1tlo + (size_t)l*HD*2*HD;
    const __nv_bfloat16* W2h   = pWn2thi + (size_t)l*HD*HD;
    const __nv_bfloat16* W2l   = pWn2tlo + (size_t)l*HD*HD;
    const float* gpl = pgp + (size_t)l*NBg*HD;

    k_ln<<<NN, 256>>>(ph, phn, phnhi, phnlo, ln_g + l*HD, ln_b + l*HD);
    // fused nps+npd (HMMA, fp32 out)
    hmma<2><<<dim3(8,10), blk, HMMA_SMEM>>>(phnhi, phnlo, Wsdh, Wsdl, HD, nullptr,
                                 nullptr,nullptr,nullptr,nullptr,nullptr,nullptr,
                                 nullptr,nullptr, pnps, pnpd);
    // edge MLP-1
    hmma<0><<<dim3(4,190), blk, HMMA_SMEM>>>(pAhi, pAlo, Wt1h, Wt1l_, KP2, be1l,
                                  pnps, pnpd, gpl, srcI, dstI, e2g, pe1hi, pe1lo, nullptr, nullptr);
    // edge MLP-2 + fused segment-sum
    k_zero<<<640, 256>>>(pagg, NN*HD);
    hmma<1><<<dim3(4,190), blk, HMMA_SMEM>>>(pe1hi, pe1lo, Wt2h, Wt2l_, HD, be2l,
                                  nullptr, nullptr, nullptr, srcI, nullptr, nullptr,
                                  nullptr, nullptr, pagg, nullptr);
    // node MLP (HMMA)
    k_ncat<<<NN, HD>>>();
    hmma<3><<<dim3(4,10), blk, HMMA_SMEM>>>(pncathi, pncatlo, W1h, W1l, 2*HD, bn1l,
                                 nullptr,nullptr,nullptr,nullptr,nullptr,nullptr,
                                 pt1hi, pt1lo, nullptr, nullptr);
    hmma<4><<<dim3(4,10), blk, HMMA_SMEM>>>(pt1hi, pt1lo, W2h, W2l, HD, bn2l,
                                 nullptr,nullptr,nullptr,nullptr,nullptr,nullptr,
                                 nullptr,nullptr, ph, nullptr);
  }

  // -------- heads --------
  k_ln<<<NN, 256>>>(ph, phn, phnhi, phnlo, fg, fb);
  k_zero<<<128, 256>>>(psum, NBg*HD);
  k_pool<<<NN, HD>>>(n2g);
  k_pos<<<NN, 96>>>(Wc, out);
  k_cell<<<NBg, 192>>>(na, Wlo, blo, out);
}

// round 17
// speedup vs baseline: 1.3586x; 1.0262x over previous
#include <cuda_runtime.h>
#include <cuda_bf16.h>
#include <math.h>
#include <stdint.h>

#define NBg  64
#define NPGC 20
#define HD   512
#define TDC  256
#define NFC  128
#define NLC  6
#define AC   100
#define NN   1280
#define EE   24320
#define KP2  800       /* 3 + 768 padded to 25*32 */
#define TWO_PI_F 6.283185307179586f

// ---------------- scratch ----------------
__device__ __nv_bfloat16 g_Ahi[(size_t)EE * KP2];
__device__ __nv_bfloat16 g_Alo[(size_t)EE * KP2];
__device__ __nv_bfloat16 g_e1hi[(size_t)EE * HD];
__device__ __nv_bfloat16 g_e1lo[(size_t)EE * HD];
__device__ __nv_bfloat16 g_Wt1hi[(size_t)NLC * HD * KP2];
__device__ __nv_bfloat16 g_Wt1lo[(size_t)NLC * HD * KP2];
__device__ __nv_bfloat16 g_Wt2hi[(size_t)NLC * HD * HD];
__device__ __nv_bfloat16 g_Wt2lo[(size_t)NLC * HD * HD];
__device__ __nv_bfloat16 g_Wsdhi[(size_t)NLC * 1024 * HD];   // [src(512) ; dst(512)] rows
__device__ __nv_bfloat16 g_Wsdlo[(size_t)NLC * 1024 * HD];
__device__ __nv_bfloat16 g_Wn1thi[(size_t)NLC * HD * 2 * HD];
__device__ __nv_bfloat16 g_Wn1tlo[(size_t)NLC * HD * 2 * HD];
__device__ __nv_bfloat16 g_Wn2thi[(size_t)NLC * HD * HD];
__device__ __nv_bfloat16 g_Wn2tlo[(size_t)NLC * HD * HD];
__device__ __nv_bfloat16 g_hnhi[NN * HD];
__device__ __nv_bfloat16 g_hnlo[NN * HD];
__device__ __nv_bfloat16 g_ncathi[NN * 2 * HD];
__device__ __nv_bfloat16 g_ncatlo[NN * 2 * HD];
__device__ __nv_bfloat16 g_t1hi[NN * HD];
__device__ __nv_bfloat16 g_t1lo[NN * HD];
__device__ float g_h[NN * HD];
__device__ float g_hn[NN * HD];
__device__ float g_nps[NN * HD];
__device__ float g_npd[NN * HD];
__device__ float g_agg[NN * HD];
__device__ float g_gp[(size_t)NLC * NBg * HD];
__device__ float g_ltl[NBg * 9];
__device__ float g_counts[NN];
__device__ float g_sum[NBg * HD];
__device__ float g_nodeproj[AC * HD];
__device__ float g_sj[HD];

__device__ __forceinline__ float siluf(float x){ return x / (1.f + expf(-x)); }

#define MMA16816(c, a, b0_, b1_) \
    asm volatile("mma.sync.aligned.m16n8k16.row.col.f32.bf16.bf16.f32 " \
        "{%0,%1,%2,%3}, {%4,%5,%6,%7}, {%8,%9}, {%0,%1,%2,%3};" \
        : "+f"((c)[0]), "+f"((c)[1]), "+f"((c)[2]), "+f"((c)[3]) \
        : "r"((a)[0]), "r"((a)[1]), "r"((a)[2]), "r"((a)[3]), "r"(b0_), "r"(b1_))

#define LDSM_X4(r0,r1,r2,r3,addr) \
    asm volatile("ldmatrix.sync.aligned.m8n8.x4.shared.b16 {%0,%1,%2,%3}, [%4];" \
        : "=r"(r0),"=r"(r1),"=r"(r2),"=r"(r3) : "r"(addr))

__device__ __forceinline__ uint32_t smem_to_u32(const void* p) {
    uint32_t a;
    asm("{ .reg .u64 tmp; cvta.to.shared.u64 tmp, %1; cvt.u32.u64 %0, tmp; }" : "=r"(a) : "l"(p));
    return a;
}
__device__ __forceinline__ void cpa16(uint32_t dst, const void* src){
  asm volatile("cp.async.cg.shared.global [%0], [%1], 16;" :: "r"(dst), "l"(src));
}
#define CP_COMMIT() asm volatile("cp.async.commit_group;" ::: "memory")
#define CP_WAIT(N)  asm volatile("cp.async.wait_group %0;" :: "n"(N) : "memory")

// ---------------- small kernels ----------------
__global__ void k_zero(float* p, int n){
  for (int i = blockIdx.x*blockDim.x + threadIdx.x; i < n; i += gridDim.x*blockDim.x) p[i] = 0.f;
}

__global__ void k_graphprep(const float* __restrict__ lp){
  int g = blockIdx.x*blockDim.x + threadIdx.x;
  if (g >= NBg) return;
  const float LM0=1.575442910194397f, LM1=1.7017393112182617f, LM2=1.9781638383865356f;
  const float LS0=0.24437622725963593f, LS1=0.26526379585266113f, LS2=0.3535512685775757f;
  float l0 = expf(lp[g*6+0]*LS0+LM0);
  float l1 = expf(lp[g*6+1]*LS1+LM1);
  float l2 = expf(lp[g*6+2]*LS2+LM2);
  float ang[3];
  #pragma unroll
  for (int i=0;i<3;i++){
    float x = lp[g*6+3+i];
    float sg = 1.f/(1.f+expf(-x));
    ang[i] = (59.9f + 60.2f*sg) * 0.017453292519943295f;
  }
  float c0=cosf(ang[0]), c1=cosf(ang[1]), c2=cosf(ang[2]);
  float s0=sinf(ang[0]), s1=sinf(ang[1]);
  float val = (c0*c1 - c2)/(s0*s1);
  val = fminf(1.f, fmaxf(-1.f, val));
  float gs = acosf(val);
  float L[3][3];
  L[0][0]=l0*s1;            L[0][1]=0.f;             L[0][2]=l0*c1;
  L[1][0]=-l1*s0*cosf(gs);  L[1][1]=l1*s0*sinf(gs);  L[1][2]=l1*c0;
  L[2][0]=0.f;              L[2][1]=0.f;             L[2][2]=l2;
  #pragma unroll
  for (int i=0;i<3;i++)
    #pragma unroll
    for (int k=0;k<3;k++)
      g_ltl[g*9+i*3+k] = L[i][0]*L[k][0] + L[i][1]*L[k][1] + L[i][2]*L[k][2];
}

__global__ void k_sj(const float* __restrict__ Wt, const float* __restrict__ Wlat){
  int j = blockIdx.x*64 + threadIdx.x;
  float acc = 0.f;
  for (int k=0;k<TDC;k++) acc += Wt[k]*Wlat[(size_t)(512+k)*HD + j];
  g_sj[j] = acc;
}

__global__ void k_nodeproj(const float* __restrict__ Wn, const float* __restrict__ Wlat){
  int a = blockIdx.x, j = threadIdx.x;
  float acc = 0.f;
  for (int k=0;k<HD;k++) acc += Wn[a*HD+k]*Wlat[(size_t)k*HD + j];
  g_nodeproj[a*HD+j] = acc;
}

__global__ void k_hinit(const int* __restrict__ at, const int* __restrict__ n2g,
                        const float* __restrict__ t){
  int n = blockIdx.x, j = threadIdx.x;
  int a = at[n]-1; if (a < 0) a = 0;
  g_h[n*HD+j] = g_nodeproj[a*HD+j] + t[n2g[n]] * g_sj[j];
}

__device__ __forceinline__ void split_store(__nv_bfloat16* hi, __nv_bfloat16* lo, size_t idx, float v){
  __nv_bfloat16 h = __float2bfloat16(v);
  hi[idx] = h;
  lo[idx] = __float2bfloat16(v - __bfloat162float(h));
}

__global__ void k_edgeprep(const float* __restrict__ fc, const int* __restrict__ srcI,
                           const int* __restrict__ dstI, const int* __restrict__ e2gI){
  int e = blockIdx.x; int tid = threadIdx.x;  // 128 threads
  int s = srcI[e], d = dstI[e], g = e2gI[e];
  float fd[3];
  #pragma unroll
  for (int i=0;i<3;i++){
    float z = TWO_PI_F * (fc[d*3+i] - fc[s*3+i]);
    fd[i] = atan2f(sinf(z), cosf(z)) / TWO_PI_F;
  }
  size_t rb = (size_t)e*KP2;
  if (tid == 0){
    float dots[3]; float nrm = 0.f;
    #pragma unroll
    for (int i=0;i<3;i++){
      float acc = 0.f;
      #pragma unroll
      for (int j=0;j<3;j++) acc += g_ltl[g*9+i*3+j]*fd[j];
      dots[i] = acc; nrm += acc*acc;
    }
    nrm = sqrtf(nrm) + 1e-12f;
    #pragma unroll
    for (int i=0;i<3;i++) split_store(g_Ahi, g_Alo, rb+i, dots[i]/nrm);
    atomicAdd(&g_counts[s], 1.f);
  }
  if (tid >= 64 && tid < 64 + (KP2 - 771)){
    int c = 771 + tid - 64;
    g_Ahi[rb+c] = __float2bfloat16(0.f);
    g_Alo[rb+c] = __float2bfloat16(0.f);
  }
  for (int idx = tid; idx < 3*NFC; idx += blockDim.x){
    int i = idx >> 7, k = idx & 127;
    float arg = TWO_PI_F * (float)k * fd[i];
    float sv, cv; sincosf(arg, &sv, &cv);
    split_store(g_Ahi, g_Alo, rb + 3 + idx, sv);
    split_store(g_Ahi, g_Alo, rb + 3 + 384 + idx, cv);
  }
}

// ---- weight preps ----
// legacy remapped transpose for Wt1 (rows 0..2 and 1033..1800 of We1)
__global__ void k_wt1(const float* __restrict__ We1){
  int b = blockIdx.x;                // NLC*HD blocks
  int l = b >> 9, n = b & 511;
  const float* W = We1 + (size_t)l*2313*HD;
  size_t ob = (size_t)b*KP2;
  for (int k = threadIdx.x; k < KP2; k += 256){
    float v = 0.f;
    if (k < 3) v = W[(size_t)k*HD + n];
    else if (k < 771) v = W[(size_t)(k+1030)*HD + n];
    split_store(g_Wt1hi, g_Wt1lo, ob + k, v);
  }
}
// coalesced tiled transpose + split: dst[n + dstRow0][k] = src[srcRow0 + k][n], src has 512 cols
__global__ void k_tsplit(const float* __restrict__ src, int srcTotRows, int srcRow0,
                         __nv_bfloat16* __restrict__ dhi, __nv_bfloat16* __restrict__ dlo,
                         size_t dstLayerElems, int dstRow0, int dstRowLen){
  __shared__ float tile[32][33];
  int l = blockIdx.z;
  int k0 = blockIdx.x*32, n0 = blockIdx.y*32;
  const float* S = src + (size_t)l*srcTotRows*512;
  for (int i = threadIdx.y; i < 32; i += 8)
    tile[i][threadIdx.x] = S[(size_t)(srcRow0 + k0 + i)*512 + n0 + threadIdx.x];
  __syncthreads();
  __nv_bfloat16* DH = dhi + (size_t)l*dstLayerElems;
  __nv_bfloat16* DL = dlo + (size_t)l*dstLayerElems;
  for (int i = threadIdx.y; i < 32; i += 8){
    float v = tile[threadIdx.x][i];
    size_t o = (size_t)(dstRow0 + n0 + i)*dstRowLen + k0 + threadIdx.x;
    __nv_bfloat16 h = __float2bfloat16(v);
    DH[o] = h;
    DL[o] = __float2bfloat16(v - __bfloat162float(h));
  }
}

// LN -> fp32 y + bf16 hi/lo split; also zeroes agg and writes hn-half of ncat
__global__ void k_ln(const float* __restrict__ x, float* __restrict__ y,
                     __nv_bfloat16* __restrict__ yhi, __nv_bfloat16* __restrict__ ylo,
                     const float* __restrict__ gamma, const float* __restrict__ beta){
  int n = blockIdx.x, t = threadIdx.x;  // 256
  float v0 = x[n*HD+t], v1 = x[n*HD+t+256];
  __shared__ float s1[256], s2[256];
  s1[t] = v0+v1; s2[t] = v0*v0 + v1*v1;
  __syncthreads();
  for (int o=128;o>0;o>>=1){
    if (t<o){ s1[t]+=s1[t+o]; s2[t]+=s2[t+o]; }
    __syncthreads();
  }
  float mu = s1[0] * (1.f/512.f);
  float var = s2[0] * (1.f/512.f) - mu*mu;
  float rs = rsqrtf(var + 1e-5f);
  float o0 = (v0-mu)*rs*gamma[t]     + beta[t];
  float o1 = (v1-mu)*rs*gamma[t+256] + beta[t+256];
  y[n*HD+t]     = o0;
  y[n*HD+t+256] = o1;
  split_store(yhi, ylo, (size_t)n*HD+t,     o0);
  split_store(yhi, ylo, (size_t)n*HD+t+256, o1);
  // hn-half of ncat
  split_store(g_ncathi, g_ncatlo, (size_t)n*1024 + t,       o0);
  split_store(g_ncathi, g_ncatlo, (size_t)n*1024 + t + 256, o1);
  // zero agg for the upcoming segment-sum
  g_agg[n*HD+t]     = 0.f;
  g_agg[n*HD+t+256] = 0.f;
}

// all-layer gp precompute: grid (NBg, NLC)
__global__ void k_gp_all(const float* __restrict__ lp, const int* __restrict__ na,
                         const float* __restrict__ We1, const float* __restrict__ Wna){
  int g = blockIdx.x, l = blockIdx.y, j = threadIdx.x;  // 512
  const float* We1l = We1 + (size_t)l*2313*HD;
  const float* Wnal = Wna + (size_t)l*AC*HD;
  float acc = 0.f;
  #pragma unroll
  for (int k=0;k<6;k++) acc += lp[g*6+k]*We1l[(size_t)(1027+k)*HD + j];
  int nr = na[g]-1; if (nr < 0) nr = 0;
  const float* wrow = Wnal + (size_t)nr*HD;
  for (int k=0;k<HD;k++) acc += wrow[k]*We1l[(size_t)(1801+k)*HD + j];
  g_gp[(size_t)l*NBg*HD + g*HD + j] = acc;
}

// agg-half of ncat only (hn half written by k_ln)
__global__ void k_ncat(){
  int n = blockIdx.x, j = threadIdx.x;  // 512
  float c = fmaxf(g_counts[n], 1.f);
  split_store(g_ncathi, g_ncatlo, (size_t)n*1024 + 512 + j, g_agg[n*HD+j] / c);
}

__global__ void k_pool(const int* __restrict__ n2g){
  int n = blockIdx.x, j = threadIdx.x;
  atomicAdd(&g_sum[n2g[n]*HD + j], g_hn[n*HD+j]);
}

__global__ void k_pos(const float* __restrict__ Wc, float* __restrict__ out){
  int n = blockIdx.x; int w = threadIdx.x >> 5; int lane = threadIdx.x & 31;
  float acc = 0.f;
  for (int j=lane;j<HD;j+=32) acc += g_hn[n*HD+j]*Wc[j*3+w];
  #pragma unroll
  for (int o=16;o;o>>=1) acc += __shfl_down_sync(0xffffffffu, acc, o);
  if (lane==0) out[n*3+w] = acc;
}

__global__ void k_cell(const int* __restrict__ na, const float* __restrict__ Wlo,
                       const float* __restrict__ blo, float* __restrict__ out){
  int g = blockIdx.x; int o = threadIdx.x >> 5; int lane = threadIdx.x & 31;
  if (o >= 6) return;
  float nav = (float)na[g];
  float acc = 0.f;
  for (int j=lane;j<HD;j+=32){
    float s = g_sum[g*HD+j];
    acc += s*(Wlo[j*6+o]/nav + Wlo[(size_t)(HD+j)*6+o]);
  }
  #pragma unroll
  for (int off=16;off;off>>=1) acc += __shfl_down_sync(0xffffffffu, acc, off);
  if (lane==0) out[NN*3 + g*6 + o] = acc + blo[o];
}

// ---------------- HMMA GEMM: block 128x128, k-step 32, bf16 3-term split ----
// cp.async double-buffered pipeline + ldmatrix fragment loads.
// MODE 0: e1 = silu(acc + bias + nps[src]+npd[dst]+gp[e2g]) -> bf16 hi/lo (edge MLP-1)
// MODE 1: atomicAdd(agg[src], silu(acc + bias))                       (edge MLP-2)
// MODE 2: fp32 plain store; cols<512 -> fC, cols>=512 -> fC2          (nps+npd fused)
// MODE 3: silu(acc + bias) -> bf16 hi/lo                               (node t1)
// MODE 4: fC += silu(acc + bias) (fp32 residual)                       (node h)
#define SAS 40                      /* smem row stride in bf16 (32 + 8 pad) */
#define STG_ELEMS (128*SAS)         /* bf16 per array per stage */
#define STG_BYTES (4*STG_ELEMS*2)   /* 4 arrays per stage = 40960 B */
#define HMMA_SMEM (2*STG_BYTES)     /* 81920 B */
template<int MODE>
__global__ void __launch_bounds__(256,2)
hmma(const __nv_bfloat16* __restrict__ Ahi, const __nv_bfloat16* __restrict__ Alo,
     const __nv_bfloat16* __restrict__ Bhi, const __nv_bfloat16* __restrict__ Blo,
     int KT,
     const float* __restrict__ bias,
     const float* __restrict__ nps, const float* __restrict__ npd, const float* __restrict__ gp,
     const int* __restrict__ srcI, const int* __restrict__ dstI, const int* __restrict__ e2gI,
     __nv_bfloat16* __restrict__ outhi, __nv_bfloat16* __restrict__ outlo,
     float* __restrict__ fC, float* __restrict__ fC2)
{
  extern __shared__ __nv_bfloat16 dynsmem[];
  uint32_t smbase = smem_to_u32(dynsmem);

  int tid = threadIdx.x, wid = tid >> 5, lane = tid & 31;
  int warp_m = wid & 3, warp_n = wid >> 2;     // 4 x 2 warp grid
  int rowBlock = blockIdx.y * 128;
  int colBlock = blockIdx.x * 128;

  float acc[2][8][4];
  #pragma unroll
  for (int i=0;i<2;i++)
    #pragma unroll
    for (int j=0;j<8;j++)
      #pragma unroll
      for (int q=0;q<4;q++) acc[i][j][q] = 0.f;

  // gmem load mapping: thread -> (row = tid>>1, 16-bf16 half = tid&1), 2x cp.async 16B per array
  int lrow = tid >> 1, lcol = (tid & 1) * 16;
  const __nv_bfloat16* gAh = Ahi + (size_t)(rowBlock + lrow)*KT + lcol;
  const __nv_bfloat16* gAl = Alo + (size_t)(rowBlock + lrow)*KT + lcol;
  const __nv_bfloat16* gBh = Bhi + (size_t)(colBlock + lrow)*KT + lcol;
  const __nv_bfloat16* gBl = Blo + (size_t)(colBlock + lrow)*KT + lcol;

  // ldmatrix lane offsets (bf16 units within array)
  uint32_t a_off = ((uint32_t)(warp_m*32 + (lane & 15)) * SAS + (uint32_t)((lane >> 4) * 8)) * 2;
  uint32_t b_off = ((uint32_t)(warp_n*64 + ((lane >> 4) * 8) + (lane & 7)) * SAS
                    + (uint32_t)(((lane >> 3) & 1) * 8)) * 2;

  const int nsteps = KT >> 5;
  uint32_t sidx2 = (uint32_t)(lrow*SAS + lcol) * 2;   // byte offset within array

  // stage 0
  {
    uint32_t st = smbase;
    cpa16(st + 0*STG_ELEMS*2 + sidx2,      gAh);
    cpa16(st + 0*STG_ELEMS*2 + sidx2 + 16, gAh + 8);
    cpa16(st + 1*STG_ELEMS*2 + sidx2,      gAl);
    cpa16(st + 1*STG_ELEMS*2 + sidx2 + 16, gAl + 8);
    cpa16(st + 2*STG_ELEMS*2 + sidx2,      gBh);
    cpa16(st + 2*STG_ELEMS*2 + sidx2 + 16, gBh + 8);
    cpa16(st + 3*STG_ELEMS*2 + sidx2,      gBl);
    cpa16(st + 3*STG_ELEMS*2 + sidx2 + 16, gBl + 8);
    CP_COMMIT();
  }

  for (int s = 0; s < nsteps; s++){
    if (s + 1 < nsteps){
      int o = (s+1)*32;
      uint32_t st = smbase + ((s+1) & 1) * STG_BYTES;
      cpa16(st + 0*STG_ELEMS*2 + sidx2,      gAh + o);
      cpa16(st + 0*STG_ELEMS*2 + sidx2 + 16, gAh + o + 8);
      cpa16(st + 1*STG_ELEMS*2 + sidx2,      gAl + o);
      cpa16(st + 1*STG_ELEMS*2 + sidx2 + 16, gAl + o + 8);
      cpa16(st + 2*STG_ELEMS*2 + sidx2,      gBh + o);
      cpa16(st + 2*STG_ELEMS*2 + sidx2 + 16, gBh + o + 8);
      cpa16(st + 3*STG_ELEMS*2 + sidx2,      gBl + o);
      cpa16(st + 3*STG_ELEMS*2 + sidx2 + 16, gBl + o + 8);
      CP_COMMIT();
      CP_WAIT(1);     // stage s complete; s+1 may still be in flight
    } else {
      CP_WAIT(0);
    }
    __syncthreads();

    uint32_t cur = smbase + (s & 1) * STG_BYTES;
    uint32_t cAh = cur + 0*STG_ELEMS*2;
    uint32_t cAl = cur + 1*STG_ELEMS*2;
    uint32_t cBh = cur + 2*STG_ELEMS*2;
    uint32_t cBl = cur + 3*STG_ELEMS*2;

    #pragma unroll
    for (int kk = 0; kk < 32; kk += 16){
      uint32_t ah[2][4], al[2][4], bh[4][4], bl[4][4];
      #pragma unroll
      for (int mt = 0; mt < 2; mt++){
        uint32_t off = a_off + (uint32_t)(mt*16*SAS + kk)*2;
        LDSM_X4(ah[mt][0], ah[mt][1], ah[mt][2], ah[mt][3], cAh + off);
        LDSM_X4(al[mt][0], al[mt][1], al[mt][2], al[mt][3], cAl + off);
      }
      #pragma unroll
      for (int ng = 0; ng < 4; ng++){
        uint32_t off = b_off + (uint32_t)(ng*16*SAS + kk)*2;
        LDSM_X4(bh[ng][0], bh[ng][1], bh[ng][2], bh[ng][3], cBh + off);
        LDSM_X4(bl[ng][0], bl[ng][1], bl[ng][2], bl[ng][3], cBl + off);
      }
      #pragma unroll
      for (int nt = 0; nt < 8; nt++){
        int ng = nt >> 1, sel = (nt & 1) * 2;
        #pragma unroll
        for (int mt = 0; mt < 2; mt++){
          MMA16816(acc[mt][nt], ah[mt], bh[ng][sel], bh[ng][sel+1]);
          MMA16816(acc[mt][nt], ah[mt], bl[ng][sel], bl[ng][sel+1]);
          MMA16816(acc[mt][nt], al[mt], bh[ng][sel], bh[ng][sel+1]);
        }
      }
    }
    __syncthreads();
  }

  // ---- epilogue ----
  int cbase = colBlock + warp_n*64 + (lane & 3)*2;
  float2 bvv[8];
  if (MODE != 2){
    #pragma unroll
    for (int nt = 0; nt < 8; nt++) bvv[nt] = *(const float2*)(bias + cbase + nt*8);
  }

  #pragma unroll
  for (int mt = 0; mt < 2; mt++){
    #pragma unroll
    for (int h = 0; h < 2; h++){
      int r = rowBlock + warp_m*32 + mt*16 + (lane >> 2) + h*8;
      if (MODE == 0){
        int s2 = srcI[r], d2 = dstI[r], g2 = e2gI[r];
        const float* np_s = nps + (size_t)s2*HD;
        const float* np_d = npd + (size_t)d2*HD;
        const float* gpp  = gp  + (size_t)g2*HD;
        __nv_bfloat16* oh = outhi + (size_t)r*HD;
        __nv_bfloat16* ol = outlo + (size_t)r*HD;
        #pragma unroll
        for (int nt = 0; nt < 8; nt++){
          int c = cbase + nt*8;
          float2 sv = *(const float2*)(np_s + c);
          float2 dv = *(const float2*)(np_d + c);
          float2 gv = *(const float2*)(gpp + c);
          float v0 = siluf(acc[mt][nt][h*2+0] + bvv[nt].x + sv.x + dv.x + gv.x);
          float v1 = siluf(acc[mt][nt][h*2+1] + bvv[nt].y + sv.y + dv.y + gv.y);
          __nv_bfloat16 h0 = __float2bfloat16(v0);
          __nv_bfloat16 h1 = __float2bfloat16(v1);
          __nv_bfloat162 hip; hip.x = h0; hip.y = h1;
          __nv_bfloat162 lop;
          lop.x = __float2bfloat16(v0 - __bfloat162float(h0));
          lop.y = __float2bfloat16(v1 - __bfloat162float(h1));
          *(__nv_bfloat162*)(oh + c) = hip;
          *(__nv_bfloat162*)(ol + c) = lop;
        }
      } else if (MODE == 1){
        int s2 = srcI[r];
        float* ao = fC + (size_t)s2*HD;
        #pragma unroll
        for (int nt = 0; nt < 8; nt++){
          int c = cbase + nt*8;
          atomicAdd(ao + c,     siluf(acc[mt][nt][h*2+0] + bvv[nt].x));
          atomicAdd(ao + c + 1, siluf(acc[mt][nt][h*2+1] + bvv[nt].y));
        }
      } else if (MODE == 2){
        float* fo = (cbase < 512) ? (fC + (size_t)r*HD) : (fC2 + (size_t)r*HD - 512);
        #pragma unroll
        for (int nt = 0; nt < 8; nt++){
          int c = cbase + nt*8;
          fo[c]     = acc[mt][nt][h*2+0];
          fo[c + 1] = acc[mt][nt][h*2+1];
        }
      } else if (MODE == 3){
        __nv_bfloat16* oh = outhi + (size_t)r*HD;
        __nv_bfloat16* ol = outlo + (size_t)r*HD;
        #pragma unroll
        for (int nt = 0; nt < 8; nt++){
          int c = cbase + nt*8;
          float v0 = siluf(acc[mt][nt][h*2+0] + bvv[nt].x);
          float v1 = siluf(acc[mt][nt][h*2+1] + bvv[nt].y);
          __nv_bfloat16 h0 = __float2bfloat16(v0);
          __nv_bfloat16 h1 = __float2bfloat16(v1);
          __nv_bfloat162 hip; hip.x = h0; hip.y = h1;
          __nv_bfloat162 lop;
          lop.x = __float2bfloat16(v0 - __bfloat162float(h0));
          lop.y = __float2bfloat16(v1 - __bfloat162float(h1));
          *(__nv_bfloat162*)(oh + c) = hip;
          *(__nv_bfloat162*)(ol + c) = lop;
        }
      } else {  // MODE 4
        float* fo = fC + (size_t)r*HD;
        #pragma unroll
        for (int nt = 0; nt < 8; nt++){
          int c = cbase + nt*8;
          fo[c]     += siluf(acc[mt][nt][h*2+0] + bvv[nt].x);
          fo[c + 1] += siluf(acc[mt][nt][h*2+1] + bvv[nt].y);
        }
      }
    }
  }
}

// ---------------- host ----------------
extern "C" void kernel_launch(void* const* d_in, const int* in_sizes, int n_in,
                              void* d_out, int out_size) {
  const float* t    = (const float*)d_in[0];
  const float* fc   = (const float*)d_in[1];
  const float* lp   = (const float*)d_in[2];
  const int*   at   = (const int*)d_in[3];
  const int*   na   = (const int*)d_in[4];
  const int*   n2g  = (const int*)d_in[5];
  const int*   eidx = (const int*)d_in[6];
  const int*   e2g  = (const int*)d_in[7];
  const float* W_node   = (const float*)d_in[8];
  const float* W_time   = (const float*)d_in[9];
  const float* W_latent = (const float*)d_in[10];
  const float* ln_g = (const float*)d_in[11];
  const float* ln_b = (const float*)d_in[12];
  const float* We1  = (const float*)d_in[13];
  const float* be1  = (const float*)d_in[14];
  const float* We2  = (const float*)d_in[15];
  const float* be2  = (const float*)d_in[16];
  const float* Wn1  = (const float*)d_in[17];
  const float* bn1  = (const float*)d_in[18];
  const float* Wn2  = (const float*)d_in[19];
  const float* bn2  = (const float*)d_in[20];
  const float* Wna  = (const float*)d_in[21];
  const float* fg   = (const float*)d_in[22];
  const float* fb   = (const float*)d_in[23];
  const float* Wc   = (const float*)d_in[24];
  const float* Wlo  = (const float*)d_in[25];
  const float* blo  = (const float*)d_in[26];
  const int* srcI = eidx;
  const int* dstI = eidx + EE;
  float* out = (float*)d_out;

  float *ph,*phn,*pnps,*pnpd,*pagg,*pgp,*pcounts,*psum;
  __nv_bfloat16 *pAhi,*pAlo,*pe1hi,*pe1lo,*pWt1hi,*pWt1lo,*pWt2hi,*pWt2lo;
  __nv_bfloat16 *pWsdhi,*pWsdlo,*pWn1thi,*pWn1tlo,*pWn2thi,*pWn2tlo;
  __nv_bfloat16 *phnhi,*phnlo,*pncathi,*pncatlo,*pt1hi,*pt1lo;
  cudaGetSymbolAddress((void**)&ph, g_h);
  cudaGetSymbolAddress((void**)&phn, g_hn);
  cudaGetSymbolAddress((void**)&pnps, g_nps);
  cudaGetSymbolAddress((void**)&pnpd, g_npd);
  cudaGetSymbolAddress((void**)&pagg, g_agg);
  cudaGetSymbolAddress((void**)&pgp, g_gp);
  cudaGetSymbolAddress((void**)&pcounts, g_counts);
  cudaGetSymbolAddress((void**)&psum, g_sum);
  cudaGetSymbolAddress((void**)&pAhi, g_Ahi);
  cudaGetSymbolAddress((void**)&pAlo, g_Alo);
  cudaGetSymbolAddress((void**)&pe1hi, g_e1hi);
  cudaGetSymbolAddress((void**)&pe1lo, g_e1lo);
  cudaGetSymbolAddress((void**)&pWt1hi, g_Wt1hi);
  cudaGetSymbolAddress((void**)&pWt1lo, g_Wt1lo);
  cudaGetSymbolAddress((void**)&pWt2hi, g_Wt2hi);
  cudaGetSymbolAddress((void**)&pWt2lo, g_Wt2lo);
  cudaGetSymbolAddress((void**)&pWsdhi, g_Wsdhi);
  cudaGetSymbolAddress((void**)&pWsdlo, g_Wsdlo);
  cudaGetSymbolAddress((void**)&pWn1thi, g_Wn1thi);
  cudaGetSymbolAddress((void**)&pWn1tlo, g_Wn1tlo);
  cudaGetSymbolAddress((void**)&pWn2thi, g_Wn2thi);
  cudaGetSymbolAddress((void**)&pWn2tlo, g_Wn2tlo);
  cudaGetSymbolAddress((void**)&phnhi, g_hnhi);
  cudaGetSymbolAddress((void**)&phnlo, g_hnlo);
  cudaGetSymbolAddress((void**)&pncathi, g_ncathi);
  cudaGetSymbolAddress((void**)&pncatlo, g_ncatlo);
  cudaGetSymbolAddress((void**)&pt1hi, g_t1hi);
  cudaGetSymbolAddress((void**)&pt1lo, g_t1lo);

  static bool attr_done = false;
  if (!attr_done){
    cudaFuncSetAttribute(hmma<0>, cudaFuncAttributeMaxDynamicSharedMemorySize, HMMA_SMEM);
    cudaFuncSetAttribute(hmma<1>, cudaFuncAttributeMaxDynamicSharedMemorySize, HMMA_SMEM);
    cudaFuncSetAttribute(hmma<2>, cudaFuncAttributeMaxDynamicSharedMemorySize, HMMA_SMEM);
    cudaFuncSetAttribute(hmma<3>, cudaFuncAttributeMaxDynamicSharedMemorySize, HMMA_SMEM);
    cudaFuncSetAttribute(hmma<4>, cudaFuncAttributeMaxDynamicSharedMemorySize, HMMA_SMEM);
    attr_done = true;
  }

  dim3 blk(256);
  dim3 tblk(32,8);

  // -------- precompute --------
  k_graphprep<<<1, NBg>>>(lp);
  k_zero<<<8, 256>>>(pcounts, NN);
  k_edgeprep<<<EE, 128>>>(fc, srcI, dstI, e2g);
  k_wt1<<<NLC*HD, 256>>>(We1);
  // coalesced transposes: dst[n][k] = src[srcRow0+k][n]
  k_tsplit<<<dim3(16,16,NLC), tblk>>>(We2, 512, 0,       pWt2hi, pWt2lo, (size_t)512*512,  0,   512);
  k_tsplit<<<dim3(16,16,NLC), tblk>>>(We1, 2313, 3,      pWsdhi, pWsdlo, (size_t)1024*512, 0,   512);
  k_tsplit<<<dim3(16,16,NLC), tblk>>>(We1, 2313, 515,    pWsdhi, pWsdlo, (size_t)1024*512, 512, 512);
  k_tsplit<<<dim3(32,16,NLC), tblk>>>(Wn1, 1024, 0,      pWn1thi, pWn1tlo, (size_t)512*1024, 0,  1024);
  k_tsplit<<<dim3(16,16,NLC), tblk>>>(Wn2, 512, 0,       pWn2thi, pWn2tlo, (size_t)512*512,  0,   512);
  k_gp_all<<<dim3(NBg, NLC), HD>>>(lp, na, We1, Wna);
  k_nodeproj<<<AC, HD>>>(W_node, W_latent);
  k_sj<<<8, 64>>>(W_time, W_latent);
  k_hinit<<<NN, HD>>>(at, n2g, t);

  // -------- layers --------
  for (int l = 0; l < NLC; l++){
    const float* be1l = be1 + l*HD;
    const float* be2l = be2 + l*HD;
    const float* bn1l = bn1 + l*HD;
    const float* bn2l = bn2 + l*HD;
    const __nv_bfloat16* Wt1h  = pWt1hi + (size_t)l*HD*KP2;
    const __nv_bfloat16* Wt1l_ = pWt1lo + (size_t)l*HD*KP2;
    const __nv_bfloat16* Wt2h  = pWt2hi + (size_t)l*HD*HD;
    const __nv_bfloat16* Wt2l_ = pWt2lo + (size_t)l*HD*HD;
    const __nv_bfloat16* Wsdh  = pWsdhi + (size_t)l*1024*HD;
    const __nv_bfloat16* Wsdl  = pWsdlo + (size_t)l*1024*HD;
    const __nv_bfloat16* W1h   = pWn1thi + (size_t)l*HD*2*HD;
    const __nv_bfloat16* W1l   = pWn1tlo + (size_t)l*HD*2*HD;
    const __nv_bfloat16* W2h   = pWn2thi + (size_t)l*HD*HD;
    const __nv_bfloat16* W2l   = pWn2tlo + (size_t)l*HD*HD;
    const float* gpl = pgp + (size_t)l*NBg*HD;

    k_ln<<<NN, 256>>>(ph, phn, phnhi, phnlo, ln_g + l*HD, ln_b + l*HD);
    // fused nps+npd (HMMA, fp32 out)
    hmma<2><<<dim3(8,10), blk, HMMA_SMEM>>>(phnhi, phnlo, Wsdh, Wsdl, HD, nullptr,
                                 nullptr,nullptr,nullptr,nullptr,nullptr,nullptr,
                                 nullptr,nullptr, pnps, pnpd);
    // edge MLP-1
    hmma<0><<<dim3(4,190), blk, HMMA_SMEM>>>(pAhi, pAlo, Wt1h, Wt1l_, KP2, be1l,
                                  pnps, pnpd, gpl, srcI, dstI, e2g, pe1hi, pe1lo, nullptr, nullptr);
    // edge MLP-2 + fused segment-sum (agg zeroed by k_ln)
    hmma<1><<<dim3(4,190), blk, HMMA_SMEM>>>(pe1hi, pe1lo, Wt2h, Wt2l_, HD, be2l,
                                  nullptr, nullptr, nullptr, srcI, nullptr, nullptr,
                                  nullptr, nullptr, pagg, nullptr);
    // node MLP (HMMA)
    k_ncat<<<NN, HD>>>();
    hmma<3><<<dim3(4,10), blk, HMMA_SMEM>>>(pncathi, pncatlo, W1h, W1l, 2*HD, bn1l,
                                 nullptr,nullptr,nullptr,nullptr,nullptr,nullptr,
                                 pt1hi, pt1lo, nullptr, nullptr);
    hmma<4><<<dim3(4,10), blk, HMMA_SMEM>>>(pt1hi, pt1lo, W2h, W2l, HD, bn2l,
                                 nullptr,nullptr,nullptr,nullptr,nullptr,nullptr,
                                 nullptr,nullptr, ph, nullptr);
  }

  // -------- heads --------
  k_ln<<<NN, 256>>>(ph, phn, phnhi, phnlo, fg, fb);
  k_zero<<<128, 256>>>(psum, NBg*HD);
  k_pool<<<NN, HD>>>(n2g);
  k_pos<<<NN, 96>>>(Wc, out);
  k_cell<<<NBg, 192>>>(na, Wlo, blo, out);
}